// round 13
// baseline (speedup 1.0000x reference)
#include <cuda_runtime.h>
#include <cuda_bf16.h>
#include <math.h>
#include <stdint.h>

#define T_TOK 16384
#define DMOD  512
#define LSEQ  2048
#define BATCH 8
#define HIN   128
#define GCH   16
#define CLEN  128          // LSEQ / GCH
#define ST_PLANE (BATCH*GCH*DMOD)

// ---------------- scratch (__device__ globals; no cudaMalloc) ----------------
__device__ float g_H  [(size_t)T_TOK*DMOD];   // encoder out == skip (fp32)
__device__ float g_HN [(size_t)T_TOK*DMOD];   // layernorm out (fp32)
__device__ float g_BU [(size_t)T_TOK*2*DMOD]; // Bu interleaved (re,im) fp32
__device__ float g_ST [4*ST_PLANE];           // scan chunk states
__device__ float g_IN [4*ST_PLANE];           // scan chunk init states

// bf16 hi/lo activation pairs
__device__ __nv_bfloat16 g_XH [(size_t)T_TOK*HIN],  g_XL [(size_t)T_TOK*HIN];
__device__ __nv_bfloat16 g_HNH[(size_t)T_TOK*DMOD], g_HNL[(size_t)T_TOK*DMOD];
__device__ __nv_bfloat16 g_XRH[(size_t)T_TOK*DMOD], g_XRL[(size_t)T_TOK*DMOD];
__device__ __nv_bfloat16 g_XIH[(size_t)T_TOK*DMOD], g_XIL[(size_t)T_TOK*DMOD];
__device__ __nv_bfloat16 g_YH [(size_t)T_TOK*DMOD], g_YL [(size_t)T_TOK*DMOD];
__device__ __nv_bfloat16 g_H2H[(size_t)T_TOK*DMOD], g_H2L[(size_t)T_TOK*DMOD];

// bf16 hi/lo weight pairs
__device__ __nv_bfloat16 w_CEH [DMOD*HIN],    w_CEL [DMOD*HIN];   // folded W_enc@W_in
__device__ __nv_bfloat16 w_BUH [2*DMOD*DMOD], w_BUL [2*DMOD*DMOD]; // interleaved [B_re;B_im]
__device__ __nv_bfloat16 w_CRH [DMOD*DMOD],   w_CRL [DMOD*DMOD];
__device__ __nv_bfloat16 w_CIH [DMOD*DMOD],   w_CIL [DMOD*DMOD];   // pre-negated
__device__ __nv_bfloat16 w_GLH [2*DMOD*DMOD], w_GLL [2*DMOD*DMOD]; // interleaved [gw1;gw2]
__device__ __nv_bfloat16 w_ODH [HIN*DMOD],    w_ODL [HIN*DMOD];   // folded W_out@W_dec
__device__ float g_BCE[DMOD];   // folded bias: W_enc@b_in + b_enc
__device__ float g_BOD[HIN];    // folded bias: W_out@b_dec + b_out

// ---------------- helpers ----------------
__device__ __forceinline__ float gelu_tanh(float x) {
    float x3 = x * x * x;
    return 0.5f * x * (1.f + tanhf(0.7978845608028654f * (x + 0.044715f * x3)));
}
__device__ __forceinline__ float sigmoid_f(float x) { return 1.f / (1.f + expf(-x)); }

__device__ __forceinline__ void split_pair(float a, float b, uint32_t& h, uint32_t& l) {
    __nv_bfloat16 ha = __float2bfloat16(a), hb = __float2bfloat16(b);
    __nv_bfloat162 th; th.x = ha; th.y = hb;
    __nv_bfloat162 tl;
    tl.x = __float2bfloat16(a - __bfloat162float(ha));
    tl.y = __float2bfloat16(b - __bfloat162float(hb));
    h = *reinterpret_cast<uint32_t*>(&th);
    l = *reinterpret_cast<uint32_t*>(&tl);
}
__device__ __forceinline__ uint32_t smem_u32(const void* p) {
    uint32_t a;
    asm("{ .reg .u64 t; cvta.to.shared.u64 t, %1; cvt.u32.u64 %0, t; }" : "=r"(a) : "l"(p));
    return a;
}
__device__ __forceinline__ void cp16(uint32_t smem, const void* g) {
    asm volatile("cp.async.cg.shared.global [%0], [%1], 16;" :: "r"(smem), "l"(g));
}

#define LDSM4(r, addr)                                                          \
    asm volatile("ldmatrix.sync.aligned.m8n8.x4.shared.b16 {%0,%1,%2,%3}, [%4];"\
        : "=r"((r)[0]), "=r"((r)[1]), "=r"((r)[2]), "=r"((r)[3]) : "r"(addr))

#define MMA16816(d, a, b)                                                       \
    asm volatile("mma.sync.aligned.m16n8k16.row.col.f32.bf16.bf16.f32 "        \
        "{%0,%1,%2,%3}, {%4,%5,%6,%7}, {%8,%9}, {%0,%1,%2,%3};"                \
        : "+f"((d)[0]), "+f"((d)[1]), "+f"((d)[2]), "+f"((d)[3])               \
        : "r"((a)[0]), "r"((a)[1]), "r"((a)[2]), "r"((a)[3]),                  \
          "r"((b)[0]), "r"((b)[1]))

// ---------------- weight folding: C = A(M x J) @ B(J x N) -> bf16 hi/lo ----------------
// grid (M/4, N/128), block 128. Each block: 4 rows x 128 cols.
__global__ __launch_bounds__(128)
void fold_gemm(const float* __restrict__ A, const float* __restrict__ B,
               int J, int N,
               __nv_bfloat16* __restrict__ oh, __nv_bfloat16* __restrict__ ol)
{
    const int r0 = blockIdx.x * 4;
    const int c  = blockIdx.y * 128 + threadIdx.x;
    float a0 = 0.f, a1 = 0.f, a2 = 0.f, a3 = 0.f;
    for (int j = 0; j < J; j++) {
        float b = B[(size_t)j * N + c];
        a0 = fmaf(A[(size_t)(r0+0)*J + j], b, a0);
        a1 = fmaf(A[(size_t)(r0+1)*J + j], b, a1);
        a2 = fmaf(A[(size_t)(r0+2)*J + j], b, a2);
        a3 = fmaf(A[(size_t)(r0+3)*J + j], b, a3);
    }
#pragma unroll
    for (int r = 0; r < 4; r++) {
        float v = (r == 0) ? a0 : (r == 1) ? a1 : (r == 2) ? a2 : a3;
        __nv_bfloat16 h = __float2bfloat16(v);
        size_t gi = (size_t)(r0 + r) * N + c;
        oh[gi] = h;
        ol[gi] = __float2bfloat16(v - __bfloat162float(h));
    }
}

// folded bias: out[i] = sum_j A[i,j]*bin[j] + badd[i]
__global__ __launch_bounds__(128)
void fold_bias(const float* __restrict__ A, const float* __restrict__ bin,
               const float* __restrict__ badd, int J, int M, float* __restrict__ out)
{
    int i = blockIdx.x * 128 + threadIdx.x;
    if (i >= M) return;
    float acc = badd[i];
    for (int j = 0; j < J; j++) acc = fmaf(A[(size_t)i * J + j], bin[j], acc);
    out[i] = acc;
}

// ---------------- batched fp32 -> (hi, lo) bf16 conversion ----------------
// Per-job row remap for interleaved dests: dest_quad = off + (off>>7)*extra + dbase
#define NJOBS 7
struct ConvArgs {
    const float4* src[NJOBS];
    uint2* dh[NJOBS];
    uint2* dl[NJOBS];
    float sgn[NJOBS];
    int extra[NJOBS];
    int dbase[NJOBS];
    int start[NJOBS + 1];
};

__global__ __launch_bounds__(256)
void conv_all(ConvArgs a)
{
    int i = blockIdx.x * 256 + threadIdx.x;
    if (i >= a.start[NJOBS]) return;
    int j = 0;
#pragma unroll
    for (int k = 1; k < NJOBS; k++) j += (i >= a.start[k]);
    int off = i - a.start[j];
    float4 v = a.src[j][off];
    float s = a.sgn[j];
    int dq = off + (off >> 7) * a.extra[j] + a.dbase[j];
    uint2 uh, ul;
    split_pair(s * v.x, s * v.y, uh.x, ul.x);
    split_pair(s * v.z, s * v.w, uh.y, ul.y);
    a.dh[j][dq] = uh;
    a.dl[j][dq] = ul;
}

// ---------------- split-bf16 GEMM on the tensor pipe (mma.sync) ----------------
// C[m,n] = sum_k A[m,k]*W[n,k]; A=AH+AL, W=BH+BL (bf16 splits); fp32 accum.
// 3-term: ah*bh + al*bh + ah*bl.
// CTA tile 128x128, K-chunk 32, cp.async double-buffered (2 x 40KB SMEM).
// EPI 0: v = acc (+bias[col]); store fp32 and/or bf16 hi/lo
// EPI 1: dual accumulate (A,W)+(A2,W2); v = gelu(acc + e1[col]*e2[row,col])
// EPI 2: GLU-pair interleaved: h2 = e2 + (acc1+bias)*sigmoid(acc2+e1), half-width out
#define TILE_STRIDE 80
#define TILE_BYTES  10240
#define BUF_BYTES   40960
#define GEMM_SMEM   (2*BUF_BYTES)

__device__ __forceinline__ void load_chunk_cp(
    uint32_t sb, int buf, int tid, int bm, int bn, int K,
    const __nv_bfloat16* ah, const __nv_bfloat16* al,
    const __nv_bfloat16* bh, const __nv_bfloat16* bl, int k0)
{
    const int lrow = tid >> 2;
    const int lcb  = (tid & 3) * 16;
    const int lel  = lcb >> 1;
    const __nv_bfloat16* srcs[4] = {ah, al, bh, bl};
    const int br4[4] = {bm, bm, bn, bn};
#pragma unroll
    for (int sub = 0; sub < 4; ++sub)
#pragma unroll
        for (int it = 0; it < 2; ++it) {
            int row = lrow + it * 64;
            uint32_t dst = sb + buf * BUF_BYTES + sub * TILE_BYTES + row * TILE_STRIDE + lcb;
            cp16(dst, srcs[sub] + (size_t)(br4[sub] + row) * K + k0 + lel);
        }
}

template<int EPI>
__global__ __launch_bounds__(256, 2)
void mma_gemm(const __nv_bfloat16* __restrict__ AH, const __nv_bfloat16* __restrict__ AL,
              const __nv_bfloat16* __restrict__ BH, const __nv_bfloat16* __restrict__ BL,
              const __nv_bfloat16* __restrict__ A2H, const __nv_bfloat16* __restrict__ A2L,
              const __nv_bfloat16* __restrict__ B2H, const __nv_bfloat16* __restrict__ B2L,
              const float* __restrict__ bias,
              const float* __restrict__ e1, const float* __restrict__ e2,
              float* __restrict__ outF,
              __nv_bfloat16* __restrict__ outH, __nv_bfloat16* __restrict__ outL,
              int N, int K)
{
    extern __shared__ char smem[];
    const uint32_t sb = smem_u32(smem);
    const int tid = threadIdx.x, wid = tid >> 5, lane = tid & 31;
    const int bm = blockIdx.y * 128, bn = blockIdx.x * 128;
    const int wm = (wid & 3) * 32, wn = (wid >> 2) * 64;

    float acc[2][8][4];
#pragma unroll
    for (int i = 0; i < 2; i++)
#pragma unroll
        for (int j = 0; j < 8; j++)
#pragma unroll
            for (int k = 0; k < 4; k++) acc[i][j][k] = 0.f;

    const int a_row  = lane & 15;
    const int a_byte = (lane >> 4) * 16;
    const int bg     = lane >> 3;
    const int b_row  = (bg >> 1) * 8 + (lane & 7);
    const int b_byte = (bg & 1) * 16;

    const int kchunks = K / 32;
    const int nchunks = (EPI == 1 ? 2 : 1) * kchunks;

    #define SEL(c, ah_, al_, bh_, bl_, k0_)                                     \
        if (EPI == 1 && (c) >= kchunks) {                                       \
            ah_ = A2H; al_ = A2L; bh_ = B2H; bl_ = B2L; k0_ = ((c) - kchunks) * 32; \
        } else { ah_ = AH; al_ = AL; bh_ = BH; bl_ = BL; k0_ = (c) * 32; }

    {
        const __nv_bfloat16 *ah, *al, *bh, *bl; int k0;
        SEL(0, ah, al, bh, bl, k0);
        load_chunk_cp(sb, 0, tid, bm, bn, K, ah, al, bh, bl, k0);
        asm volatile("cp.async.commit_group;" ::: "memory");
    }

    for (int c = 0; c < nchunks; ++c) {
        const int buf = c & 1;
        if (c + 1 < nchunks) {
            const __nv_bfloat16 *ah, *al, *bh, *bl; int k0;
            SEL(c + 1, ah, al, bh, bl, k0);
            load_chunk_cp(sb, (c + 1) & 1, tid, bm, bn, K, ah, al, bh, bl, k0);
        }
        asm volatile("cp.async.commit_group;" ::: "memory");
        asm volatile("cp.async.wait_group 1;" ::: "memory");
        __syncthreads();

        const uint32_t tb = sb + buf * BUF_BYTES;
#pragma unroll
        for (int ks = 0; ks < 2; ++ks) {
            uint32_t af[2][4], bf[8][2], xf[2][4];
#pragma unroll
            for (int mt = 0; mt < 2; ++mt) {
                uint32_t ad = tb + (wm + mt * 16 + a_row) * TILE_STRIDE + ks * 32 + a_byte;
                LDSM4(af[mt], ad);
            }
#pragma unroll
            for (int j = 0; j < 4; ++j) {
                uint32_t ad = tb + 2 * TILE_BYTES + (wn + j * 16 + b_row) * TILE_STRIDE + ks * 32 + b_byte;
                uint32_t r[4]; LDSM4(r, ad);
                bf[2*j][0] = r[0]; bf[2*j][1] = r[1];
                bf[2*j+1][0] = r[2]; bf[2*j+1][1] = r[3];
            }
#pragma unroll
            for (int mt = 0; mt < 2; ++mt)
#pragma unroll
                for (int nt = 0; nt < 8; ++nt) MMA16816(acc[mt][nt], af[mt], bf[nt]);
#pragma unroll
            for (int mt = 0; mt < 2; ++mt) {
                uint32_t ad = tb + TILE_BYTES + (wm + mt * 16 + a_row) * TILE_STRIDE + ks * 32 + a_byte;
                LDSM4(xf[mt], ad);
            }
#pragma unroll
            for (int mt = 0; mt < 2; ++mt)
#pragma unroll
                for (int nt = 0; nt < 8; ++nt) MMA16816(acc[mt][nt], xf[mt], bf[nt]);
#pragma unroll
            for (int j = 0; j < 4; ++j) {
                uint32_t ad = tb + 3 * TILE_BYTES + (wn + j * 16 + b_row) * TILE_STRIDE + ks * 32 + b_byte;
                uint32_t r[4]; LDSM4(r, ad);
                bf[2*j][0] = r[0]; bf[2*j][1] = r[1];
                bf[2*j+1][0] = r[2]; bf[2*j+1][1] = r[3];
            }
#pragma unroll
            for (int mt = 0; mt < 2; ++mt)
#pragma unroll
                for (int nt = 0; nt < 8; ++nt) MMA16816(acc[mt][nt], af[mt], bf[nt]);
        }
        __syncthreads();
    }
    #undef SEL

    // ---- stage accumulators to SMEM (128 x 132 fp32), then fused epilogue ----
    float* stg = (float*)smem;
#pragma unroll
    for (int mt = 0; mt < 2; ++mt)
#pragma unroll
        for (int nt = 0; nt < 8; ++nt)
#pragma unroll
            for (int h = 0; h < 2; ++h) {
                int r  = wm + mt * 16 + (lane >> 2) + h * 8;
                int cc = wn + nt * 8 + (lane & 3) * 2;
                *(float2*)(stg + r * 132 + cc) =
                    make_float2(acc[mt][nt][h * 2], acc[mt][nt][h * 2 + 1]);
            }
    __syncthreads();

    for (int i = tid; i < 128 * 32; i += 256) {
        int r = i >> 5, c4 = (i & 31) * 4;
        float4 v = *(const float4*)(stg + r * 132 + c4);
        const int row = bm + r, col = bn + c4;
        if (EPI == 2) {
            const int co = col >> 1;
            float2 sk = *(const float2*)(e2 + (size_t)row * DMOD + co);
            float h2a = sk.x + (v.x + bias[co])     * sigmoid_f(v.y + e1[co]);
            float h2b = sk.y + (v.z + bias[co + 1]) * sigmoid_f(v.w + e1[co + 1]);
            uint32_t hh, ll;
            split_pair(h2a, h2b, hh, ll);
            size_t gi = (size_t)row * DMOD + co;
            *(uint32_t*)(outH + gi) = hh;
            *(uint32_t*)(outL + gi) = ll;
            continue;
        }
        if (EPI == 0) {
            if (bias) {
                float4 bb = *(const float4*)(bias + col);
                v.x += bb.x; v.y += bb.y; v.z += bb.z; v.w += bb.w;
            }
        } else if (EPI == 1) {
            float4 dd = *(const float4*)(e1 + col);
            float4 hh = *(const float4*)(e2 + (size_t)row * DMOD + col);
            v.x = gelu_tanh(v.x + dd.x * hh.x);
            v.y = gelu_tanh(v.y + dd.y * hh.y);
            v.z = gelu_tanh(v.z + dd.z * hh.z);
            v.w = gelu_tanh(v.w + dd.w * hh.w);
        }
        size_t gi = (size_t)row * N + col;
        if (outF) *(float4*)(outF + gi) = v;
        if (outH) {
            uint2 uh, ul;
            split_pair(v.x, v.y, uh.x, ul.x);
            split_pair(v.z, v.w, uh.y, ul.y);
            *(uint2*)(outH + gi) = uh;
            *(uint2*)(outL + gi) = ul;
        }
    }
}

// ---------------- LayerNorm (+ bf16 hi/lo) ----------------
__global__ __launch_bounds__(128)
void ln_kernel(const float* __restrict__ h, const float* __restrict__ g,
               const float* __restrict__ b, float* __restrict__ out,
               __nv_bfloat16* __restrict__ oh, __nv_bfloat16* __restrict__ ol)
{
    const int row = blockIdx.x, t = threadIdx.x;
    float4 v = ((const float4*)(h + (size_t)row * DMOD))[t];
    float s  = v.x + v.y + v.z + v.w;
    float sq = v.x*v.x + v.y*v.y + v.z*v.z + v.w*v.w;
#pragma unroll
    for (int o = 16; o > 0; o >>= 1) {
        s  += __shfl_down_sync(0xffffffff, s,  o);
        sq += __shfl_down_sync(0xffffffff, sq, o);
    }
    __shared__ float ss[4], ssq[4];
    const int w = t >> 5, l = t & 31;
    if (l == 0) { ss[w] = s; ssq[w] = sq; }
    __syncthreads();
    if (t == 0) {
        float S = ss[0]+ss[1]+ss[2]+ss[3], SQ = ssq[0]+ssq[1]+ssq[2]+ssq[3];
        float mu = S * (1.f/DMOD);
        ss[0] = mu;
        ssq[0] = rsqrtf(SQ * (1.f/DMOD) - mu*mu + 1e-5f);
    }
    __syncthreads();
    const float mu = ss[0], rstd = ssq[0];
    float4 gv = ((const float4*)g)[t], bv = ((const float4*)b)[t];
    float4 o4;
    o4.x = (v.x-mu)*rstd*gv.x + bv.x;
    o4.y = (v.y-mu)*rstd*gv.y + bv.y;
    o4.z = (v.z-mu)*rstd*gv.z + bv.z;
    o4.w = (v.w-mu)*rstd*gv.w + bv.w;
    size_t gi = (size_t)row * DMOD + t * 4;
    *(float4*)(out + gi) = o4;
    uint2 uh, ul;
    split_pair(o4.x, o4.y, uh.x, ul.x);
    split_pair(o4.z, o4.w, uh.y, ul.y);
    *(uint2*)(oh + gi) = uh;
    *(uint2*)(ol + gi) = ul;
}

// ---------------- chunked LinOSS-IM scan (interleaved Bu) ----------------
__device__ __forceinline__ void scan_params(int n, const float* __restrict__ A_diag,
                                            const float* __restrict__ ls,
                                            float& m11, float& m12, float& m21, float& m22,
                                            float& c1, float& c2)
{
    float Ad = fmaxf(A_diag[n], 0.f);
    float dt = 1.f / (1.f + expf(-ls[n]));
    float S  = 1.f / (1.f + dt*dt*Ad);
    m11 = 1.f - dt*dt*Ad*S; m12 = -dt*Ad*S; m21 = dt*S; m22 = S;
    c1 = m11*dt; c2 = m21*dt;
}

__global__ __launch_bounds__(256)
void scanA(const float* __restrict__ bu,
           const float* __restrict__ A_diag, const float* __restrict__ ls,
           float* __restrict__ st)
{
    const int n  = ((blockIdx.x & 1) << 8) + threadIdx.x;
    const int bg = blockIdx.x >> 1;
    const int g  = bg & (GCH - 1), b = bg >> 4;
    float m11, m12, m21, m22, c1, c2;
    scan_params(n, A_diag, ls, m11, m12, m21, m22, c1, c2);
    float zr = 0.f, zi = 0.f, xr = 0.f, xi = 0.f;
    size_t idx = ((size_t)b * LSEQ + (size_t)g * CLEN) * (2*DMOD) + 2*n;
    for (int t = 0; t < CLEN; t++, idx += 2*DMOD) {
        float2 bv = *(const float2*)(bu + idx);
        float nzr = fmaf(m11, zr, fmaf(m12, xr, c1 * bv.x));
        float nzi = fmaf(m11, zi, fmaf(m12, xi, c1 * bv.y));
        float nxr = fmaf(m21, zr, fmaf(m22, xr, c2 * bv.x));
        float nxi = fmaf(m21, zi, fmaf(m22, xi, c2 * bv.y));
        zr = nzr; zi = nzi; xr = nxr; xi = nxi;
    }
    int si = bg * DMOD + n;
    st[si] = zr; st[ST_PLANE + si] = xr;
    st[2*ST_PLANE + si] = zi; st[3*ST_PLANE + si] = xi;
}

__global__ __launch_bounds__(256)
void scanB(const float* __restrict__ A_diag, const float* __restrict__ ls,
           const float* __restrict__ st, float* __restrict__ init)
{
    const int tid = blockIdx.x * 256 + threadIdx.x;
    const int n = tid & (DMOD - 1), b = tid >> 9;
    float m11, m12, m21, m22, c1, c2;
    scan_params(n, A_diag, ls, m11, m12, m21, m22, c1, c2);
    float a11 = m11, a12 = m12, a21 = m21, a22 = m22;
#pragma unroll
    for (int i = 0; i < 7; i++) {
        float n11 = a11*a11 + a12*a21, n12 = a11*a12 + a12*a22;
        float n21 = a21*a11 + a22*a21, n22 = a21*a12 + a22*a22;
        a11 = n11; a12 = n12; a21 = n21; a22 = n22;
    }
    float pzr = 0.f, pxr = 0.f, pzi = 0.f, pxi = 0.f;
    for (int g = 0; g < GCH; g++) {
        int si = (b * GCH + g) * DMOD + n;
        init[si] = pzr; init[ST_PLANE + si] = pxr;
        init[2*ST_PLANE + si] = pzi; init[3*ST_PLANE + si] = pxi;
        float szr = st[si], sxr = st[ST_PLANE + si];
        float szi = st[2*ST_PLANE + si], sxi = st[3*ST_PLANE + si];
        float nzr = a11*pzr + a12*pxr + szr, nxr = a21*pzr + a22*pxr + sxr;
        float nzi = a11*pzi + a12*pxi + szi, nxi = a21*pzi + a22*pxi + sxi;
        pzr = nzr; pxr = nxr; pzi = nzi; pxi = nxi;
    }
}

__global__ __launch_bounds__(256)
void scanC(const float* __restrict__ bu,
           const float* __restrict__ A_diag, const float* __restrict__ ls,
           const float* __restrict__ init,
           __nv_bfloat16* __restrict__ xrh, __nv_bfloat16* __restrict__ xrl,
           __nv_bfloat16* __restrict__ xih, __nv_bfloat16* __restrict__ xil)
{
    const int n  = ((blockIdx.x & 1) << 8) + threadIdx.x;
    const int bg = blockIdx.x >> 1;
    const int g  = bg & (GCH - 1), b = bg >> 4;
    float m11, m12, m21, m22, c1, c2;
    scan_params(n, A_diag, ls, m11, m12, m21, m22, c1, c2);
    int si = bg * DMOD + n;
    float zr = init[si], xr = init[ST_PLANE + si];
    float zi = init[2*ST_PLANE + si], xi = init[3*ST_PLANE + si];
    size_t idx  = ((size_t)b * LSEQ + (size_t)g * CLEN) * (2*DMOD) + 2*n;
    size_t odx  = ((size_t)b * LSEQ + (size_t)g * CLEN) * DMOD + n;
    for (int t = 0; t < CLEN; t++, idx += 2*DMOD, odx += DMOD) {
        float2 bv = *(const float2*)(bu + idx);
        float nzr = fmaf(m11, zr, fmaf(m12, xr, c1 * bv.x));
        float nzi = fmaf(m11, zi, fmaf(m12, xi, c1 * bv.y));
        float nxr = fmaf(m21, zr, fmaf(m22, xr, c2 * bv.x));
        float nxi = fmaf(m21, zi, fmaf(m22, xi, c2 * bv.y));
        zr = nzr; zi = nzi; xr = nxr; xi = nxi;
        __nv_bfloat16 hr = __float2bfloat16(xr);
        __nv_bfloat16 hi = __float2bfloat16(xi);
        xrh[odx] = hr; xrl[odx] = __float2bfloat16(xr - __bfloat162float(hr));
        xih[odx] = hi; xil[odx] = __float2bfloat16(xi - __bfloat162float(hi));
    }
}

// ---------------------------------------------------------------------------
extern "C" void kernel_launch(void* const* d_in, const int* in_sizes, int n_in,
                              void* d_out, int out_size)
{
    const float* x      = (const float*)d_in[0];
    const float* W_in   = (const float*)d_in[1];
    const float* b_in   = (const float*)d_in[2];
    const float* W_enc  = (const float*)d_in[3];
    const float* b_enc  = (const float*)d_in[4];
    const float* ln_g   = (const float*)d_in[5];
    const float* ln_b   = (const float*)d_in[6];
    const float* A_diag = (const float*)d_in[7];
    const float* lstep  = (const float*)d_in[8];
    const float* B_re   = (const float*)d_in[9];
    const float* B_im   = (const float*)d_in[10];
    const float* C_re   = (const float*)d_in[11];
    const float* C_im   = (const float*)d_in[12];
    const float* Dv     = (const float*)d_in[13];
    const float* gw1    = (const float*)d_in[14];
    const float* gb1    = (const float*)d_in[15];
    const float* gw2    = (const float*)d_in[16];
    const float* gb2    = (const float*)d_in[17];
    const float* W_dec  = (const float*)d_in[18];
    const float* b_dec  = (const float*)d_in[19];
    const float* W_out  = (const float*)d_in[20];
    const float* b_out  = (const float*)d_in[21];
    float* out = (float*)d_out;

    #define SYM(T, v, s) T* v; cudaGetSymbolAddress((void**)&v, s)
    SYM(float, H, g_H); SYM(float, HN, g_HN); SYM(float, BU, g_BU);
    SYM(float, ST, g_ST); SYM(float, IN, g_IN);
    SYM(float, BCE, g_BCE); SYM(float, BOD, g_BOD);
    SYM(__nv_bfloat16, XH, g_XH);  SYM(__nv_bfloat16, XL, g_XL);
    SYM(__nv_bfloat16, HNH, g_HNH); SYM(__nv_bfloat16, HNL, g_HNL);
    SYM(__nv_bfloat16, XRH, g_XRH); SYM(__nv_bfloat16, XRL, g_XRL);
    SYM(__nv_bfloat16, XIH, g_XIH); SYM(__nv_bfloat16, XIL, g_XIL);
    SYM(__nv_bfloat16, YH, g_YH);   SYM(__nv_bfloat16, YL, g_YL);
    SYM(__nv_bfloat16, H2H, g_H2H); SYM(__nv_bfloat16, H2L, g_H2L);
    SYM(__nv_bfloat16, CEH, w_CEH);  SYM(__nv_bfloat16, CEL, w_CEL);
    SYM(__nv_bfloat16, BUH, w_BUH);  SYM(__nv_bfloat16, BUL, w_BUL);
    SYM(__nv_bfloat16, CRH, w_CRH);  SYM(__nv_bfloat16, CRL, w_CRL);
    SYM(__nv_bfloat16, CIH, w_CIH);  SYM(__nv_bfloat16, CIL, w_CIL);
    SYM(__nv_bfloat16, GLH, w_GLH);  SYM(__nv_bfloat16, GLL, w_GLL);
    SYM(__nv_bfloat16, ODH, w_ODH);  SYM(__nv_bfloat16, ODL, w_ODL);
    #undef SYM

    cudaFuncSetAttribute(mma_gemm<0>, cudaFuncAttributeMaxDynamicSharedMemorySize, GEMM_SMEM);
    cudaFuncSetAttribute(mma_gemm<1>, cudaFuncAttributeMaxDynamicSharedMemorySize, GEMM_SMEM);
    cudaFuncSetAttribute(mma_gemm<2>, cudaFuncAttributeMaxDynamicSharedMemorySize, GEMM_SMEM);

    // ---- weight folding: W_ce = W_enc @ W_in (512x128); W_od = W_out @ W_dec (128x512) ----
    fold_gemm<<<dim3(DMOD/4, HIN/128), 128>>>(W_enc, W_in, DMOD, HIN, CEH, CEL);
    fold_gemm<<<dim3(HIN/4, DMOD/128), 128>>>(W_out, W_dec, DMOD, DMOD, ODH, ODL);
    fold_bias<<<DMOD/128, 128>>>(W_enc, b_in, b_enc, DMOD, DMOD, BCE);
    fold_bias<<<1, 128>>>(W_out, b_dec, b_out, DMOD, HIN, BOD);

    // ---- single batched conversion: remaining weights (with interleave) + x ----
    {
        const int qW = DMOD * DMOD / 4;     // 65536 quads
        const int qX = T_TOK * HIN / 4;     // 524288
        ConvArgs a;
        const float* srcs[NJOBS] = {B_re, B_im, C_re, C_im, gw1, gw2, x};
        __nv_bfloat16* dhs[NJOBS] = {BUH, BUH, CRH, CIH, GLH, GLH, XH};
        __nv_bfloat16* dls[NJOBS] = {BUL, BUL, CRL, CIL, GLL, GLL, XL};
        const int sizes[NJOBS]   = {qW, qW, qW, qW, qW, qW, qX};
        const int extras[NJOBS]  = {128, 128, 0, 0, 128, 128, 0};
        const int dbases[NJOBS]  = {0,   128, 0, 0, 0,   128, 0};
        int acc0 = 0;
        for (int j = 0; j < NJOBS; j++) {
            a.src[j] = (const float4*)srcs[j];
            a.dh[j] = (uint2*)dhs[j];
            a.dl[j] = (uint2*)dls[j];
            a.sgn[j] = (j == 3) ? -1.f : 1.f;     // C_im pre-negated
            a.extra[j] = extras[j];
            a.dbase[j] = dbases[j];
            a.start[j] = acc0;
            acc0 += sizes[j];
        }
        a.start[NJOBS] = acc0;
        conv_all<<<(acc0 + 255) / 256, 256>>>(a);
    }

    dim3 blk(256);
    dim3 g512(DMOD / 128, T_TOK / 128);       // 4 x 128
    dim3 g1024(2 * DMOD / 128, T_TOK / 128);  // 8 x 128 (fused N=1024)
    dim3 g128(HIN / 128, T_TOK / 128);        // 1 x 128

    // 1) folded in_proj+encoder (K=128) -> fp32 H (skip)
    mma_gemm<0><<<g512, blk, GEMM_SMEM>>>(XH, XL, CEH, CEL, 0,0,0,0, BCE, 0,0,
                                          H, nullptr, nullptr, DMOD, HIN);
    // 2) layernorm -> HN fp32 + bf16
    ln_kernel<<<T_TOK, 128>>>(H, ln_g, ln_b, HN, HNH, HNL);
    // 3) fused Bu projection (interleaved re/im, N=1024) -> fp32 BU
    mma_gemm<0><<<g1024, blk, GEMM_SMEM>>>(HNH, HNL, BUH, BUL, 0,0,0,0, nullptr, 0,0,
                                           BU, nullptr, nullptr, 2*DMOD, DMOD);
    // 4) chunked scan -> bf16 xs
    scanA<<<256, 256>>>(BU, A_diag, lstep, ST);
    scanB<<<16, 256>>>(A_diag, lstep, ST, IN);
    scanC<<<256, 256>>>(BU, A_diag, lstep, IN, XRH, XRL, XIH, XIL);
    // 5) y = gelu(xr@Cre^T + xi@(-Cim)^T + D*hn) -> bf16 Y
    mma_gemm<1><<<g512, blk, GEMM_SMEM>>>(XRH, XRL, CRH, CRL, XIH, XIL, CIH, CIL,
                                          nullptr, Dv, HN, nullptr, YH, YL, DMOD, DMOD);
    // 6) fused GLU (interleaved g1/g2, N=1024) -> bf16 H2 = skip + g1*sigmoid(g2)
    mma_gemm<2><<<g1024, blk, GEMM_SMEM>>>(YH, YL, GLH, GLL, 0,0,0,0, gb1, gb2, H,
                                           nullptr, H2H, H2L, 2*DMOD, DMOD);
    // 7) folded decoder+out_proj (N=128, K=512) -> fp32 out
    mma_gemm<0><<<g128, blk, GEMM_SMEM>>>(H2H, H2L, ODH, ODL, 0,0,0,0, BOD, 0,0,
                                          out, nullptr, nullptr, HIN, DMOD);
}

// round 14
// speedup vs baseline: 1.4224x; 1.4224x over previous
#include <cuda_runtime.h>
#include <cuda_bf16.h>
#include <math.h>
#include <stdint.h>

#define T_TOK 16384
#define DMOD  512
#define LSEQ  2048
#define BATCH 8
#define HIN   128
#define GCH   16
#define CLEN  128          // LSEQ / GCH
#define ST_PLANE (BATCH*GCH*DMOD)

// ---------------- scratch (__device__ globals; no cudaMalloc) ----------------
__device__ float g_H  [(size_t)T_TOK*DMOD];   // encoder out == skip (fp32)
__device__ float g_HN [(size_t)T_TOK*DMOD];   // layernorm out (fp32)
__device__ float g_BU [(size_t)T_TOK*2*DMOD]; // Bu interleaved (re,im) fp32
__device__ float g_ST [4*ST_PLANE];           // scan chunk states
__device__ float g_IN [4*ST_PLANE];           // scan chunk init states

// bf16 hi/lo activation pairs
__device__ __nv_bfloat16 g_XH [(size_t)T_TOK*HIN],  g_XL [(size_t)T_TOK*HIN];
__device__ __nv_bfloat16 g_HNH[(size_t)T_TOK*DMOD], g_HNL[(size_t)T_TOK*DMOD];
__device__ __nv_bfloat16 g_XRH[(size_t)T_TOK*DMOD], g_XRL[(size_t)T_TOK*DMOD];
__device__ __nv_bfloat16 g_XIH[(size_t)T_TOK*DMOD], g_XIL[(size_t)T_TOK*DMOD];
__device__ __nv_bfloat16 g_YH [(size_t)T_TOK*DMOD], g_YL [(size_t)T_TOK*DMOD];
__device__ __nv_bfloat16 g_H2H[(size_t)T_TOK*DMOD], g_H2L[(size_t)T_TOK*DMOD];

// bf16 hi/lo weight pairs
__device__ __nv_bfloat16 w_CEH [DMOD*HIN],    w_CEL [DMOD*HIN];   // folded W_enc@W_in
__device__ __nv_bfloat16 w_BUH [2*DMOD*DMOD], w_BUL [2*DMOD*DMOD]; // interleaved [B_re;B_im]
__device__ __nv_bfloat16 w_CRH [DMOD*DMOD],   w_CRL [DMOD*DMOD];
__device__ __nv_bfloat16 w_CIH [DMOD*DMOD],   w_CIL [DMOD*DMOD];   // pre-negated
__device__ __nv_bfloat16 w_GLH [2*DMOD*DMOD], w_GLL [2*DMOD*DMOD]; // interleaved [gw1;gw2]
__device__ __nv_bfloat16 w_ODH [HIN*DMOD],    w_ODL [HIN*DMOD];   // folded W_out@W_dec
__device__ float g_BCE[DMOD];   // folded bias: W_enc@b_in + b_enc
__device__ float g_BOD[HIN];    // folded bias: W_out@b_dec + b_out

// ---------------- helpers ----------------
__device__ __forceinline__ float gelu_tanh(float x) {
    float x3 = x * x * x;
    return 0.5f * x * (1.f + tanhf(0.7978845608028654f * (x + 0.044715f * x3)));
}
__device__ __forceinline__ float sigmoid_f(float x) { return 1.f / (1.f + expf(-x)); }

__device__ __forceinline__ void split_pair(float a, float b, uint32_t& h, uint32_t& l) {
    __nv_bfloat16 ha = __float2bfloat16(a), hb = __float2bfloat16(b);
    __nv_bfloat162 th; th.x = ha; th.y = hb;
    __nv_bfloat162 tl;
    tl.x = __float2bfloat16(a - __bfloat162float(ha));
    tl.y = __float2bfloat16(b - __bfloat162float(hb));
    h = *reinterpret_cast<uint32_t*>(&th);
    l = *reinterpret_cast<uint32_t*>(&tl);
}
__device__ __forceinline__ uint32_t smem_u32(const void* p) {
    uint32_t a;
    asm("{ .reg .u64 t; cvta.to.shared.u64 t, %1; cvt.u32.u64 %0, t; }" : "=r"(a) : "l"(p));
    return a;
}
__device__ __forceinline__ void cp16(uint32_t smem, const void* g) {
    asm volatile("cp.async.cg.shared.global [%0], [%1], 16;" :: "r"(smem), "l"(g));
}

#define LDSM4(r, addr)                                                          \
    asm volatile("ldmatrix.sync.aligned.m8n8.x4.shared.b16 {%0,%1,%2,%3}, [%4];"\
        : "=r"((r)[0]), "=r"((r)[1]), "=r"((r)[2]), "=r"((r)[3]) : "r"(addr))

#define MMA16816(d, a, b)                                                       \
    asm volatile("mma.sync.aligned.m16n8k16.row.col.f32.bf16.bf16.f32 "        \
        "{%0,%1,%2,%3}, {%4,%5,%6,%7}, {%8,%9}, {%0,%1,%2,%3};"                \
        : "+f"((d)[0]), "+f"((d)[1]), "+f"((d)[2]), "+f"((d)[3])               \
        : "r"((a)[0]), "r"((a)[1]), "r"((a)[2]), "r"((a)[3]),                  \
          "r"((b)[0]), "r"((b)[1]))

// ---------------- weight folding: C = A(M x J) @ B(J x N) -> bf16 hi/lo ----------------
// grid (M, N/128), block 128. Row broadcast A, coalesced B, 4 accumulator chains.
__global__ __launch_bounds__(128)
void fold_gemm(const float* __restrict__ A, const float* __restrict__ B,
               int J, int N,
               __nv_bfloat16* __restrict__ oh, __nv_bfloat16* __restrict__ ol)
{
    const int r = blockIdx.x;
    const int c = blockIdx.y * 128 + threadIdx.x;
    const float* Ar = A + (size_t)r * J;
    const float* Bc = B + c;
    float a0 = 0.f, a1 = 0.f, a2 = 0.f, a3 = 0.f;
    for (int j = 0; j < J; j += 4) {
        a0 = fmaf(Ar[j + 0], Bc[(size_t)(j + 0) * N], a0);
        a1 = fmaf(Ar[j + 1], Bc[(size_t)(j + 1) * N], a1);
        a2 = fmaf(Ar[j + 2], Bc[(size_t)(j + 2) * N], a2);
        a3 = fmaf(Ar[j + 3], Bc[(size_t)(j + 3) * N], a3);
    }
    float v = (a0 + a1) + (a2 + a3);
    __nv_bfloat16 h = __float2bfloat16(v);
    size_t gi = (size_t)r * N + c;
    oh[gi] = h;
    ol[gi] = __float2bfloat16(v - __bfloat162float(h));
}

// folded bias: out[i] = sum_j A[i,j]*bin[j] + badd[i]; one warp per row (coalesced)
__global__ __launch_bounds__(256)
void fold_bias(const float* __restrict__ A, const float* __restrict__ bin,
               const float* __restrict__ badd, int J, int M, float* __restrict__ out)
{
    const int warp = (blockIdx.x * 256 + threadIdx.x) >> 5;
    const int lane = threadIdx.x & 31;
    if (warp >= M) return;
    float acc = 0.f;
    for (int j = lane; j < J; j += 32)
        acc = fmaf(A[(size_t)warp * J + j], bin[j], acc);
#pragma unroll
    for (int o = 16; o > 0; o >>= 1) acc += __shfl_down_sync(0xffffffffu, acc, o);
    if (lane == 0) out[warp] = acc + badd[warp];
}

// ---------------- batched fp32 -> (hi, lo) bf16 conversion ----------------
// Per-job row remap for interleaved dests: dest_quad = off + (off>>7)*extra + dbase
#define NJOBS 7
struct ConvArgs {
    const float4* src[NJOBS];
    uint2* dh[NJOBS];
    uint2* dl[NJOBS];
    float sgn[NJOBS];
    int extra[NJOBS];
    int dbase[NJOBS];
    int start[NJOBS + 1];
};

__global__ __launch_bounds__(256)
void conv_all(ConvArgs a)
{
    int i = blockIdx.x * 256 + threadIdx.x;
    if (i >= a.start[NJOBS]) return;
    int j = 0;
#pragma unroll
    for (int k = 1; k < NJOBS; k++) j += (i >= a.start[k]);
    int off = i - a.start[j];
    float4 v = a.src[j][off];
    float s = a.sgn[j];
    int dq = off + (off >> 7) * a.extra[j] + a.dbase[j];
    uint2 uh, ul;
    split_pair(s * v.x, s * v.y, uh.x, ul.x);
    split_pair(s * v.z, s * v.w, uh.y, ul.y);
    a.dh[j][dq] = uh;
    a.dl[j][dq] = ul;
}

// ---------------- split-bf16 GEMM on the tensor pipe (mma.sync) ----------------
// C[m,n] = sum_k A[m,k]*W[n,k]; A=AH+AL, W=BH+BL (bf16 splits); fp32 accum.
// 3-term: ah*bh + al*bh + ah*bl.
// CTA tile 128x128, K-chunk 32, cp.async double-buffered (2 x 40KB SMEM).
// EPI 0: v = acc (+bias[col]); store fp32 and/or bf16 hi/lo
// EPI 1: dual accumulate (A,W)+(A2,W2); v = gelu(acc + e1[col]*e2[row,col])
// EPI 2: GLU-pair interleaved: h2 = e2 + (acc1+bias)*sigmoid(acc2+e1), half-width out
#define TILE_STRIDE 80
#define TILE_BYTES  10240
#define BUF_BYTES   40960
#define GEMM_SMEM   (2*BUF_BYTES)

__device__ __forceinline__ void load_chunk_cp(
    uint32_t sb, int buf, int tid, int bm, int bn, int K,
    const __nv_bfloat16* ah, const __nv_bfloat16* al,
    const __nv_bfloat16* bh, const __nv_bfloat16* bl, int k0)
{
    const int lrow = tid >> 2;
    const int lcb  = (tid & 3) * 16;
    const int lel  = lcb >> 1;
    const __nv_bfloat16* srcs[4] = {ah, al, bh, bl};
    const int br4[4] = {bm, bm, bn, bn};
#pragma unroll
    for (int sub = 0; sub < 4; ++sub)
#pragma unroll
        for (int it = 0; it < 2; ++it) {
            int row = lrow + it * 64;
            uint32_t dst = sb + buf * BUF_BYTES + sub * TILE_BYTES + row * TILE_STRIDE + lcb;
            cp16(dst, srcs[sub] + (size_t)(br4[sub] + row) * K + k0 + lel);
        }
}

template<int EPI>
__global__ __launch_bounds__(256, 2)
void mma_gemm(const __nv_bfloat16* __restrict__ AH, const __nv_bfloat16* __restrict__ AL,
              const __nv_bfloat16* __restrict__ BH, const __nv_bfloat16* __restrict__ BL,
              const __nv_bfloat16* __restrict__ A2H, const __nv_bfloat16* __restrict__ A2L,
              const __nv_bfloat16* __restrict__ B2H, const __nv_bfloat16* __restrict__ B2L,
              const float* __restrict__ bias,
              const float* __restrict__ e1, const float* __restrict__ e2,
              float* __restrict__ outF,
              __nv_bfloat16* __restrict__ outH, __nv_bfloat16* __restrict__ outL,
              int N, int K)
{
    extern __shared__ char smem[];
    const uint32_t sb = smem_u32(smem);
    const int tid = threadIdx.x, wid = tid >> 5, lane = tid & 31;
    const int bm = blockIdx.y * 128, bn = blockIdx.x * 128;
    const int wm = (wid & 3) * 32, wn = (wid >> 2) * 64;

    float acc[2][8][4];
#pragma unroll
    for (int i = 0; i < 2; i++)
#pragma unroll
        for (int j = 0; j < 8; j++)
#pragma unroll
            for (int k = 0; k < 4; k++) acc[i][j][k] = 0.f;

    const int a_row  = lane & 15;
    const int a_byte = (lane >> 4) * 16;
    const int bg     = lane >> 3;
    const int b_row  = (bg >> 1) * 8 + (lane & 7);
    const int b_byte = (bg & 1) * 16;

    const int kchunks = K / 32;
    const int nchunks = (EPI == 1 ? 2 : 1) * kchunks;

    #define SEL(c, ah_, al_, bh_, bl_, k0_)                                     \
        if (EPI == 1 && (c) >= kchunks) {                                       \
            ah_ = A2H; al_ = A2L; bh_ = B2H; bl_ = B2L; k0_ = ((c) - kchunks) * 32; \
        } else { ah_ = AH; al_ = AL; bh_ = BH; bl_ = BL; k0_ = (c) * 32; }

    {
        const __nv_bfloat16 *ah, *al, *bh, *bl; int k0;
        SEL(0, ah, al, bh, bl, k0);
        load_chunk_cp(sb, 0, tid, bm, bn, K, ah, al, bh, bl, k0);
        asm volatile("cp.async.commit_group;" ::: "memory");
    }

    for (int c = 0; c < nchunks; ++c) {
        const int buf = c & 1;
        if (c + 1 < nchunks) {
            const __nv_bfloat16 *ah, *al, *bh, *bl; int k0;
            SEL(c + 1, ah, al, bh, bl, k0);
            load_chunk_cp(sb, (c + 1) & 1, tid, bm, bn, K, ah, al, bh, bl, k0);
        }
        asm volatile("cp.async.commit_group;" ::: "memory");
        asm volatile("cp.async.wait_group 1;" ::: "memory");
        __syncthreads();

        const uint32_t tb = sb + buf * BUF_BYTES;
#pragma unroll
        for (int ks = 0; ks < 2; ++ks) {
            uint32_t af[2][4], bf[8][2], xf[2][4];
#pragma unroll
            for (int mt = 0; mt < 2; ++mt) {
                uint32_t ad = tb + (wm + mt * 16 + a_row) * TILE_STRIDE + ks * 32 + a_byte;
                LDSM4(af[mt], ad);
            }
#pragma unroll
            for (int j = 0; j < 4; ++j) {
                uint32_t ad = tb + 2 * TILE_BYTES + (wn + j * 16 + b_row) * TILE_STRIDE + ks * 32 + b_byte;
                uint32_t r[4]; LDSM4(r, ad);
                bf[2*j][0] = r[0]; bf[2*j][1] = r[1];
                bf[2*j+1][0] = r[2]; bf[2*j+1][1] = r[3];
            }
#pragma unroll
            for (int mt = 0; mt < 2; ++mt)
#pragma unroll
                for (int nt = 0; nt < 8; ++nt) MMA16816(acc[mt][nt], af[mt], bf[nt]);
#pragma unroll
            for (int mt = 0; mt < 2; ++mt) {
                uint32_t ad = tb + TILE_BYTES + (wm + mt * 16 + a_row) * TILE_STRIDE + ks * 32 + a_byte;
                LDSM4(xf[mt], ad);
            }
#pragma unroll
            for (int mt = 0; mt < 2; ++mt)
#pragma unroll
                for (int nt = 0; nt < 8; ++nt) MMA16816(acc[mt][nt], xf[mt], bf[nt]);
#pragma unroll
            for (int j = 0; j < 4; ++j) {
                uint32_t ad = tb + 3 * TILE_BYTES + (wn + j * 16 + b_row) * TILE_STRIDE + ks * 32 + b_byte;
                uint32_t r[4]; LDSM4(r, ad);
                bf[2*j][0] = r[0]; bf[2*j][1] = r[1];
                bf[2*j+1][0] = r[2]; bf[2*j+1][1] = r[3];
            }
#pragma unroll
            for (int mt = 0; mt < 2; ++mt)
#pragma unroll
                for (int nt = 0; nt < 8; ++nt) MMA16816(acc[mt][nt], af[mt], bf[nt]);
        }
        __syncthreads();
    }
    #undef SEL

    // ---- stage accumulators to SMEM (128 x 132 fp32), then fused epilogue ----
    float* stg = (float*)smem;
#pragma unroll
    for (int mt = 0; mt < 2; ++mt)
#pragma unroll
        for (int nt = 0; nt < 8; ++nt)
#pragma unroll
            for (int h = 0; h < 2; ++h) {
                int r  = wm + mt * 16 + (lane >> 2) + h * 8;
                int cc = wn + nt * 8 + (lane & 3) * 2;
                *(float2*)(stg + r * 132 + cc) =
                    make_float2(acc[mt][nt][h * 2], acc[mt][nt][h * 2 + 1]);
            }
    __syncthreads();

    for (int i = tid; i < 128 * 32; i += 256) {
        int r = i >> 5, c4 = (i & 31) * 4;
        float4 v = *(const float4*)(stg + r * 132 + c4);
        const int row = bm + r, col = bn + c4;
        if (EPI == 2) {
            const int co = col >> 1;
            float2 sk = *(const float2*)(e2 + (size_t)row * DMOD + co);
            float h2a = sk.x + (v.x + bias[co])     * sigmoid_f(v.y + e1[co]);
            float h2b = sk.y + (v.z + bias[co + 1]) * sigmoid_f(v.w + e1[co + 1]);
            uint32_t hh, ll;
            split_pair(h2a, h2b, hh, ll);
            size_t gi = (size_t)row * DMOD + co;
            *(uint32_t*)(outH + gi) = hh;
            *(uint32_t*)(outL + gi) = ll;
            continue;
        }
        if (EPI == 0) {
            if (bias) {
                float4 bb = *(const float4*)(bias + col);
                v.x += bb.x; v.y += bb.y; v.z += bb.z; v.w += bb.w;
            }
        } else if (EPI == 1) {
            float4 dd = *(const float4*)(e1 + col);
            float4 hh = *(const float4*)(e2 + (size_t)row * DMOD + col);
            v.x = gelu_tanh(v.x + dd.x * hh.x);
            v.y = gelu_tanh(v.y + dd.y * hh.y);
            v.z = gelu_tanh(v.z + dd.z * hh.z);
            v.w = gelu_tanh(v.w + dd.w * hh.w);
        }
        size_t gi = (size_t)row * N + col;
        if (outF) *(float4*)(outF + gi) = v;
        if (outH) {
            uint2 uh, ul;
            split_pair(v.x, v.y, uh.x, ul.x);
            split_pair(v.z, v.w, uh.y, ul.y);
            *(uint2*)(outH + gi) = uh;
            *(uint2*)(outL + gi) = ul;
        }
    }
}

// ---------------- LayerNorm (+ bf16 hi/lo) ----------------
__global__ __launch_bounds__(128)
void ln_kernel(const float* __restrict__ h, const float* __restrict__ g,
               const float* __restrict__ b, float* __restrict__ out,
               __nv_bfloat16* __restrict__ oh, __nv_bfloat16* __restrict__ ol)
{
    const int row = blockIdx.x, t = threadIdx.x;
    float4 v = ((const float4*)(h + (size_t)row * DMOD))[t];
    float s  = v.x + v.y + v.z + v.w;
    float sq = v.x*v.x + v.y*v.y + v.z*v.z + v.w*v.w;
#pragma unroll
    for (int o = 16; o > 0; o >>= 1) {
        s  += __shfl_down_sync(0xffffffff, s,  o);
        sq += __shfl_down_sync(0xffffffff, sq, o);
    }
    __shared__ float ss[4], ssq[4];
    const int w = t >> 5, l = t & 31;
    if (l == 0) { ss[w] = s; ssq[w] = sq; }
    __syncthreads();
    if (t == 0) {
        float S = ss[0]+ss[1]+ss[2]+ss[3], SQ = ssq[0]+ssq[1]+ssq[2]+ssq[3];
        float mu = S * (1.f/DMOD);
        ss[0] = mu;
        ssq[0] = rsqrtf(SQ * (1.f/DMOD) - mu*mu + 1e-5f);
    }
    __syncthreads();
    const float mu = ss[0], rstd = ssq[0];
    float4 gv = ((const float4*)g)[t], bv = ((const float4*)b)[t];
    float4 o4;
    o4.x = (v.x-mu)*rstd*gv.x + bv.x;
    o4.y = (v.y-mu)*rstd*gv.y + bv.y;
    o4.z = (v.z-mu)*rstd*gv.z + bv.z;
    o4.w = (v.w-mu)*rstd*gv.w + bv.w;
    size_t gi = (size_t)row * DMOD + t * 4;
    *(float4*)(out + gi) = o4;
    uint2 uh, ul;
    split_pair(o4.x, o4.y, uh.x, ul.x);
    split_pair(o4.z, o4.w, uh.y, ul.y);
    *(uint2*)(oh + gi) = uh;
    *(uint2*)(ol + gi) = ul;
}

// ---------------- chunked LinOSS-IM scan (interleaved Bu) ----------------
__device__ __forceinline__ void scan_params(int n, const float* __restrict__ A_diag,
                                            const float* __restrict__ ls,
                                            float& m11, float& m12, float& m21, float& m22,
                                            float& c1, float& c2)
{
    float Ad = fmaxf(A_diag[n], 0.f);
    float dt = 1.f / (1.f + expf(-ls[n]));
    float S  = 1.f / (1.f + dt*dt*Ad);
    m11 = 1.f - dt*dt*Ad*S; m12 = -dt*Ad*S; m21 = dt*S; m22 = S;
    c1 = m11*dt; c2 = m21*dt;
}

__global__ __launch_bounds__(256)
void scanA(const float* __restrict__ bu,
           const float* __restrict__ A_diag, const float* __restrict__ ls,
           float* __restrict__ st)
{
    const int n  = ((blockIdx.x & 1) << 8) + threadIdx.x;
    const int bg = blockIdx.x >> 1;
    const int g  = bg & (GCH - 1), b = bg >> 4;
    float m11, m12, m21, m22, c1, c2;
    scan_params(n, A_diag, ls, m11, m12, m21, m22, c1, c2);
    float zr = 0.f, zi = 0.f, xr = 0.f, xi = 0.f;
    size_t idx = ((size_t)b * LSEQ + (size_t)g * CLEN) * (2*DMOD) + 2*n;
    for (int t = 0; t < CLEN; t++, idx += 2*DMOD) {
        float2 bv = *(const float2*)(bu + idx);
        float nzr = fmaf(m11, zr, fmaf(m12, xr, c1 * bv.x));
        float nzi = fmaf(m11, zi, fmaf(m12, xi, c1 * bv.y));
        float nxr = fmaf(m21, zr, fmaf(m22, xr, c2 * bv.x));
        float nxi = fmaf(m21, zi, fmaf(m22, xi, c2 * bv.y));
        zr = nzr; zi = nzi; xr = nxr; xi = nxi;
    }
    int si = bg * DMOD + n;
    st[si] = zr; st[ST_PLANE + si] = xr;
    st[2*ST_PLANE + si] = zi; st[3*ST_PLANE + si] = xi;
}

__global__ __launch_bounds__(256)
void scanB(const float* __restrict__ A_diag, const float* __restrict__ ls,
           const float* __restrict__ st, float* __restrict__ init)
{
    const int tid = blockIdx.x * 256 + threadIdx.x;
    const int n = tid & (DMOD - 1), b = tid >> 9;
    float m11, m12, m21, m22, c1, c2;
    scan_params(n, A_diag, ls, m11, m12, m21, m22, c1, c2);
    float a11 = m11, a12 = m12, a21 = m21, a22 = m22;
#pragma unroll
    for (int i = 0; i < 7; i++) {
        float n11 = a11*a11 + a12*a21, n12 = a11*a12 + a12*a22;
        float n21 = a21*a11 + a22*a21, n22 = a21*a12 + a22*a22;
        a11 = n11; a12 = n12; a21 = n21; a22 = n22;
    }
    float pzr = 0.f, pxr = 0.f, pzi = 0.f, pxi = 0.f;
    for (int g = 0; g < GCH; g++) {
        int si = (b * GCH + g) * DMOD + n;
        init[si] = pzr; init[ST_PLANE + si] = pxr;
        init[2*ST_PLANE + si] = pzi; init[3*ST_PLANE + si] = pxi;
        float szr = st[si], sxr = st[ST_PLANE + si];
        float szi = st[2*ST_PLANE + si], sxi = st[3*ST_PLANE + si];
        float nzr = a11*pzr + a12*pxr + szr, nxr = a21*pzr + a22*pxr + sxr;
        float nzi = a11*pzi + a12*pxi + szi, nxi = a21*pzi + a22*pxi + sxi;
        pzr = nzr; pxr = nxr; pzi = nzi; pxi = nxi;
    }
}

__global__ __launch_bounds__(256)
void scanC(const float* __restrict__ bu,
           const float* __restrict__ A_diag, const float* __restrict__ ls,
           const float* __restrict__ init,
           __nv_bfloat16* __restrict__ xrh, __nv_bfloat16* __restrict__ xrl,
           __nv_bfloat16* __restrict__ xih, __nv_bfloat16* __restrict__ xil)
{
    const int n  = ((blockIdx.x & 1) << 8) + threadIdx.x;
    const int bg = blockIdx.x >> 1;
    const int g  = bg & (GCH - 1), b = bg >> 4;
    float m11, m12, m21, m22, c1, c2;
    scan_params(n, A_diag, ls, m11, m12, m21, m22, c1, c2);
    int si = bg * DMOD + n;
    float zr = init[si], xr = init[ST_PLANE + si];
    float zi = init[2*ST_PLANE + si], xi = init[3*ST_PLANE + si];
    size_t idx  = ((size_t)b * LSEQ + (size_t)g * CLEN) * (2*DMOD) + 2*n;
    size_t odx  = ((size_t)b * LSEQ + (size_t)g * CLEN) * DMOD + n;
    for (int t = 0; t < CLEN; t++, idx += 2*DMOD, odx += DMOD) {
        float2 bv = *(const float2*)(bu + idx);
        float nzr = fmaf(m11, zr, fmaf(m12, xr, c1 * bv.x));
        float nzi = fmaf(m11, zi, fmaf(m12, xi, c1 * bv.y));
        float nxr = fmaf(m21, zr, fmaf(m22, xr, c2 * bv.x));
        float nxi = fmaf(m21, zi, fmaf(m22, xi, c2 * bv.y));
        zr = nzr; zi = nzi; xr = nxr; xi = nxi;
        __nv_bfloat16 hr = __float2bfloat16(xr);
        __nv_bfloat16 hi = __float2bfloat16(xi);
        xrh[odx] = hr; xrl[odx] = __float2bfloat16(xr - __bfloat162float(hr));
        xih[odx] = hi; xil[odx] = __float2bfloat16(xi - __bfloat162float(hi));
    }
}

// ---------------------------------------------------------------------------
extern "C" void kernel_launch(void* const* d_in, const int* in_sizes, int n_in,
                              void* d_out, int out_size)
{
    const float* x      = (const float*)d_in[0];
    const float* W_in   = (const float*)d_in[1];
    const float* b_in   = (const float*)d_in[2];
    const float* W_enc  = (const float*)d_in[3];
    const float* b_enc  = (const float*)d_in[4];
    const float* ln_g   = (const float*)d_in[5];
    const float* ln_b   = (const float*)d_in[6];
    const float* A_diag = (const float*)d_in[7];
    const float* lstep  = (const float*)d_in[8];
    const float* B_re   = (const float*)d_in[9];
    const float* B_im   = (const float*)d_in[10];
    const float* C_re   = (const float*)d_in[11];
    const float* C_im   = (const float*)d_in[12];
    const float* Dv     = (const float*)d_in[13];
    const float* gw1    = (const float*)d_in[14];
    const float* gb1    = (const float*)d_in[15];
    const float* gw2    = (const float*)d_in[16];
    const float* gb2    = (const float*)d_in[17];
    const float* W_dec  = (const float*)d_in[18];
    const float* b_dec  = (const float*)d_in[19];
    const float* W_out  = (const float*)d_in[20];
    const float* b_out  = (const float*)d_in[21];
    float* out = (float*)d_out;

    #define SYM(T, v, s) T* v; cudaGetSymbolAddress((void**)&v, s)
    SYM(float, H, g_H); SYM(float, HN, g_HN); SYM(float, BU, g_BU);
    SYM(float, ST, g_ST); SYM(float, IN, g_IN);
    SYM(float, BCE, g_BCE); SYM(float, BOD, g_BOD);
    SYM(__nv_bfloat16, XH, g_XH);  SYM(__nv_bfloat16, XL, g_XL);
    SYM(__nv_bfloat16, HNH, g_HNH); SYM(__nv_bfloat16, HNL, g_HNL);
    SYM(__nv_bfloat16, XRH, g_XRH); SYM(__nv_bfloat16, XRL, g_XRL);
    SYM(__nv_bfloat16, XIH, g_XIH); SYM(__nv_bfloat16, XIL, g_XIL);
    SYM(__nv_bfloat16, YH, g_YH);   SYM(__nv_bfloat16, YL, g_YL);
    SYM(__nv_bfloat16, H2H, g_H2H); SYM(__nv_bfloat16, H2L, g_H2L);
    SYM(__nv_bfloat16, CEH, w_CEH);  SYM(__nv_bfloat16, CEL, w_CEL);
    SYM(__nv_bfloat16, BUH, w_BUH);  SYM(__nv_bfloat16, BUL, w_BUL);
    SYM(__nv_bfloat16, CRH, w_CRH);  SYM(__nv_bfloat16, CRL, w_CRL);
    SYM(__nv_bfloat16, CIH, w_CIH);  SYM(__nv_bfloat16, CIL, w_CIL);
    SYM(__nv_bfloat16, GLH, w_GLH);  SYM(__nv_bfloat16, GLL, w_GLL);
    SYM(__nv_bfloat16, ODH, w_ODH);  SYM(__nv_bfloat16, ODL, w_ODL);
    #undef SYM

    cudaFuncSetAttribute(mma_gemm<0>, cudaFuncAttributeMaxDynamicSharedMemorySize, GEMM_SMEM);
    cudaFuncSetAttribute(mma_gemm<1>, cudaFuncAttributeMaxDynamicSharedMemorySize, GEMM_SMEM);
    cudaFuncSetAttribute(mma_gemm<2>, cudaFuncAttributeMaxDynamicSharedMemorySize, GEMM_SMEM);

    // ---- weight folding (fast): W_ce = W_enc@W_in (512x128); W_od = W_out@W_dec (128x512) ----
    fold_gemm<<<dim3(DMOD, HIN/128), 128>>>(W_enc, W_in, DMOD, HIN, CEH, CEL);
    fold_gemm<<<dim3(HIN, DMOD/128), 128>>>(W_out, W_dec, DMOD, DMOD, ODH, ODL);
    fold_bias<<<DMOD/8, 256>>>(W_enc, b_in, b_enc, DMOD, DMOD, BCE);
    fold_bias<<<HIN/8, 256>>>(W_out, b_dec, b_out, DMOD, HIN, BOD);

    // ---- single batched conversion: remaining weights (with interleave) + x ----
    {
        const int qW = DMOD * DMOD / 4;     // 65536 quads
        const int qX = T_TOK * HIN / 4;     // 524288
        ConvArgs a;
        const float* srcs[NJOBS] = {B_re, B_im, C_re, C_im, gw1, gw2, x};
        __nv_bfloat16* dhs[NJOBS] = {BUH, BUH, CRH, CIH, GLH, GLH, XH};
        __nv_bfloat16* dls[NJOBS] = {BUL, BUL, CRL, CIL, GLL, GLL, XL};
        const int sizes[NJOBS]   = {qW, qW, qW, qW, qW, qW, qX};
        const int extras[NJOBS]  = {128, 128, 0, 0, 128, 128, 0};
        const int dbases[NJOBS]  = {0,   128, 0, 0, 0,   128, 0};
        int acc0 = 0;
        for (int j = 0; j < NJOBS; j++) {
            a.src[j] = (const float4*)srcs[j];
            a.dh[j] = (uint2*)dhs[j];
            a.dl[j] = (uint2*)dls[j];
            a.sgn[j] = (j == 3) ? -1.f : 1.f;     // C_im pre-negated
            a.extra[j] = extras[j];
            a.dbase[j] = dbases[j];
            a.start[j] = acc0;
            acc0 += sizes[j];
        }
        a.start[NJOBS] = acc0;
        conv_all<<<(acc0 + 255) / 256, 256>>>(a);
    }

    dim3 blk(256);
    dim3 g512(DMOD / 128, T_TOK / 128);       // 4 x 128
    dim3 g1024(2 * DMOD / 128, T_TOK / 128);  // 8 x 128 (fused N=1024)
    dim3 g128(HIN / 128, T_TOK / 128);        // 1 x 128

    // 1) folded in_proj+encoder (K=128) -> fp32 H (skip)
    mma_gemm<0><<<g512, blk, GEMM_SMEM>>>(XH, XL, CEH, CEL, 0,0,0,0, BCE, 0,0,
                                          H, nullptr, nullptr, DMOD, HIN);
    // 2) layernorm -> HN fp32 + bf16
    ln_kernel<<<T_TOK, 128>>>(H, ln_g, ln_b, HN, HNH, HNL);
    // 3) fused Bu projection (interleaved re/im, N=1024) -> fp32 BU
    mma_gemm<0><<<g1024, blk, GEMM_SMEM>>>(HNH, HNL, BUH, BUL, 0,0,0,0, nullptr, 0,0,
                                           BU, nullptr, nullptr, 2*DMOD, DMOD);
    // 4) chunked scan -> bf16 xs
    scanA<<<256, 256>>>(BU, A_diag, lstep, ST);
    scanB<<<16, 256>>>(A_diag, lstep, ST, IN);
    scanC<<<256, 256>>>(BU, A_diag, lstep, IN, XRH, XRL, XIH, XIL);
    // 5) y = gelu(xr@Cre^T + xi@(-Cim)^T + D*hn) -> bf16 Y
    mma_gemm<1><<<g512, blk, GEMM_SMEM>>>(XRH, XRL, CRH, CRL, XIH, XIL, CIH, CIL,
                                          nullptr, Dv, HN, nullptr, YH, YL, DMOD, DMOD);
    // 6) fused GLU (interleaved g1/g2, N=1024) -> bf16 H2 = skip + g1*sigmoid(g2)
    mma_gemm<2><<<g1024, blk, GEMM_SMEM>>>(YH, YL, GLH, GLL, 0,0,0,0, gb1, gb2, H,
                                           nullptr, H2H, H2L, 2*DMOD, DMOD);
    // 7) folded decoder+out_proj (N=128, K=512) -> fp32 out
    mma_gemm<0><<<g128, blk, GEMM_SMEM>>>(H2H, H2L, ODH, ODL, 0,0,0,0, BOD, 0,0,
                                          out, nullptr, nullptr, HIN, DMOD);
}

// round 16
// speedup vs baseline: 1.4357x; 1.0093x over previous
#include <cuda_runtime.h>
#include <cuda_bf16.h>
#include <math.h>
#include <stdint.h>

#define T_TOK 16384
#define DMOD  512
#define LSEQ  2048
#define BATCH 8
#define HIN   128
#define GCH   16
#define CLEN  128          // LSEQ / GCH
#define ST_PLANE (BATCH*GCH*DMOD)

// ---------------- scratch (__device__ globals; no cudaMalloc) ----------------
__device__ float g_H  [(size_t)T_TOK*DMOD];   // encoder out == skip (fp32)
__device__ float g_HN [(size_t)T_TOK*DMOD];   // layernorm out (fp32)
__device__ float g_BU [(size_t)T_TOK*2*DMOD]; // Bu interleaved (re,im) fp32
__device__ float g_ST [4*ST_PLANE];           // scan chunk states
__device__ float g_IN [4*ST_PLANE];           // scan chunk init states

// bf16 hi/lo activation pairs
__device__ __nv_bfloat16 g_XH [(size_t)T_TOK*HIN],  g_XL [(size_t)T_TOK*HIN];
__device__ __nv_bfloat16 g_HNH[(size_t)T_TOK*DMOD], g_HNL[(size_t)T_TOK*DMOD];
__device__ __nv_bfloat16 g_XRH[(size_t)T_TOK*DMOD], g_XRL[(size_t)T_TOK*DMOD];
__device__ __nv_bfloat16 g_XIH[(size_t)T_TOK*DMOD], g_XIL[(size_t)T_TOK*DMOD];
__device__ __nv_bfloat16 g_YH [(size_t)T_TOK*DMOD], g_YL [(size_t)T_TOK*DMOD];
__device__ __nv_bfloat16 g_H2H[(size_t)T_TOK*DMOD], g_H2L[(size_t)T_TOK*DMOD];

// bf16 hi/lo weight pairs
__device__ __nv_bfloat16 w_CEH [DMOD*HIN],    w_CEL [DMOD*HIN];   // folded W_enc@W_in
__device__ __nv_bfloat16 w_BUH [2*DMOD*DMOD], w_BUL [2*DMOD*DMOD]; // interleaved [B_re;B_im]
__device__ __nv_bfloat16 w_CRH [DMOD*DMOD],   w_CRL [DMOD*DMOD];
__device__ __nv_bfloat16 w_CIH [DMOD*DMOD],   w_CIL [DMOD*DMOD];   // pre-negated
__device__ __nv_bfloat16 w_GLH [2*DMOD*DMOD], w_GLL [2*DMOD*DMOD]; // interleaved [gw1;gw2]
__device__ __nv_bfloat16 w_ODH [HIN*DMOD],    w_ODL [HIN*DMOD];   // folded W_out@W_dec
__device__ float g_BCE[DMOD];   // folded bias: W_enc@b_in + b_enc
__device__ float g_BOD[HIN];    // folded bias: W_out@b_dec + b_out

// ---------------- helpers ----------------
__device__ __forceinline__ float gelu_tanh(float x) {
    float x3 = x * x * x;
    return 0.5f * x * (1.f + tanhf(0.7978845608028654f * (x + 0.044715f * x3)));
}
__device__ __forceinline__ float sigmoid_f(float x) { return 1.f / (1.f + expf(-x)); }

__device__ __forceinline__ void split_pair(float a, float b, uint32_t& h, uint32_t& l) {
    __nv_bfloat16 ha = __float2bfloat16(a), hb = __float2bfloat16(b);
    __nv_bfloat162 th; th.x = ha; th.y = hb;
    __nv_bfloat162 tl;
    tl.x = __float2bfloat16(a - __bfloat162float(ha));
    tl.y = __float2bfloat16(b - __bfloat162float(hb));
    h = *reinterpret_cast<uint32_t*>(&th);
    l = *reinterpret_cast<uint32_t*>(&tl);
}
__device__ __forceinline__ uint32_t smem_u32(const void* p) {
    uint32_t a;
    asm("{ .reg .u64 t; cvta.to.shared.u64 t, %1; cvt.u32.u64 %0, t; }" : "=r"(a) : "l"(p));
    return a;
}
__device__ __forceinline__ void cp16(uint32_t smem, const void* g) {
    asm volatile("cp.async.cg.shared.global [%0], [%1], 16;" :: "r"(smem), "l"(g));
}

#define LDSM4(r, addr)                                                          \
    asm volatile("ldmatrix.sync.aligned.m8n8.x4.shared.b16 {%0,%1,%2,%3}, [%4];"\
        : "=r"((r)[0]), "=r"((r)[1]), "=r"((r)[2]), "=r"((r)[3]) : "r"(addr))

#define MMA16816(d, a, b)                                                       \
    asm volatile("mma.sync.aligned.m16n8k16.row.col.f32.bf16.bf16.f32 "        \
        "{%0,%1,%2,%3}, {%4,%5,%6,%7}, {%8,%9}, {%0,%1,%2,%3};"                \
        : "+f"((d)[0]), "+f"((d)[1]), "+f"((d)[2]), "+f"((d)[3])               \
        : "r"((a)[0]), "r"((a)[1]), "r"((a)[2]), "r"((a)[3]),                  \
          "r"((b)[0]), "r"((b)[1]))

// ---------------- weight folding: C = A(M x J) @ B(J x N) -> bf16 hi/lo ----------------
// grid (M, N/128), block 128. Row broadcast A, coalesced B, 4 accumulator chains.
__global__ __launch_bounds__(128)
void fold_gemm(const float* __restrict__ A, const float* __restrict__ B,
               int J, int N,
               __nv_bfloat16* __restrict__ oh, __nv_bfloat16* __restrict__ ol)
{
    const int r = blockIdx.x;
    const int c = blockIdx.y * 128 + threadIdx.x;
    const float* Ar = A + (size_t)r * J;
    const float* Bc = B + c;
    float a0 = 0.f, a1 = 0.f, a2 = 0.f, a3 = 0.f;
    for (int j = 0; j < J; j += 4) {
        a0 = fmaf(Ar[j + 0], Bc[(size_t)(j + 0) * N], a0);
        a1 = fmaf(Ar[j + 1], Bc[(size_t)(j + 1) * N], a1);
        a2 = fmaf(Ar[j + 2], Bc[(size_t)(j + 2) * N], a2);
        a3 = fmaf(Ar[j + 3], Bc[(size_t)(j + 3) * N], a3);
    }
    float v = (a0 + a1) + (a2 + a3);
    __nv_bfloat16 h = __float2bfloat16(v);
    size_t gi = (size_t)r * N + c;
    oh[gi] = h;
    ol[gi] = __float2bfloat16(v - __bfloat162float(h));
}

// folded bias: out[i] = sum_j A[i,j]*bin[j] + badd[i]; one warp per row (coalesced)
__global__ __launch_bounds__(256)
void fold_bias(const float* __restrict__ A, const float* __restrict__ bin,
               const float* __restrict__ badd, int J, int M, float* __restrict__ out)
{
    const int warp = (blockIdx.x * 256 + threadIdx.x) >> 5;
    const int lane = threadIdx.x & 31;
    if (warp >= M) return;
    float acc = 0.f;
    for (int j = lane; j < J; j += 32)
        acc = fmaf(A[(size_t)warp * J + j], bin[j], acc);
#pragma unroll
    for (int o = 16; o > 0; o >>= 1) acc += __shfl_down_sync(0xffffffffu, acc, o);
    if (lane == 0) out[warp] = acc + badd[warp];
}

// ---------------- batched fp32 -> (hi, lo) bf16 conversion ----------------
// Per-job row remap for interleaved dests: dest_quad = off + (off>>7)*extra + dbase
#define NJOBS 7
struct ConvArgs {
    const float4* src[NJOBS];
    uint2* dh[NJOBS];
    uint2* dl[NJOBS];
    float sgn[NJOBS];
    int extra[NJOBS];
    int dbase[NJOBS];
    int start[NJOBS + 1];
};

__global__ __launch_bounds__(256)
void conv_all(ConvArgs a)
{
    int i = blockIdx.x * 256 + threadIdx.x;
    if (i >= a.start[NJOBS]) return;
    int j = 0;
#pragma unroll
    for (int k = 1; k < NJOBS; k++) j += (i >= a.start[k]);
    int off = i - a.start[j];
    float4 v = a.src[j][off];
    float s = a.sgn[j];
    int dq = off + (off >> 7) * a.extra[j] + a.dbase[j];
    uint2 uh, ul;
    split_pair(s * v.x, s * v.y, uh.x, ul.x);
    split_pair(s * v.z, s * v.w, uh.y, ul.y);
    a.dh[j][dq] = uh;
    a.dl[j][dq] = ul;
}

// ---------------- split-bf16 GEMM on the tensor pipe (mma.sync) ----------------
// C[m,n] = sum_k A[m,k]*W[n,k]; A=AH+AL, W=BH+BL (bf16 splits); fp32 accum.
// 3-term: ah*bh + al*bh + ah*bl.
// CTA tile 128x128, K-chunk 32, cp.async double-buffered (2 x 40KB SMEM).
// EPI 0: v = acc (+bias[col]); store fp32 and/or bf16 hi/lo
// EPI 1: dual accumulate (A,W)+(A2,W2); v = gelu(acc + e1[col]*e2[row,col])
// EPI 2: GLU-pair interleaved: h2 = e2 + (acc1+bias)*sigmoid(acc2+e1), half-width out
#define TILE_STRIDE 80
#define TILE_BYTES  10240
#define BUF_BYTES   40960
#define GEMM_SMEM   (2*BUF_BYTES)

__device__ __forceinline__ void load_chunk_cp(
    uint32_t sb, int buf, int tid, int bm, int bn, int K,
    const __nv_bfloat16* ah, const __nv_bfloat16* al,
    const __nv_bfloat16* bh, const __nv_bfloat16* bl, int k0)
{
    const int lrow = tid >> 2;
    const int lcb  = (tid & 3) * 16;
    const int lel  = lcb >> 1;
    const __nv_bfloat16* srcs[4] = {ah, al, bh, bl};
    const int br4[4] = {bm, bm, bn, bn};
#pragma unroll
    for (int sub = 0; sub < 4; ++sub)
#pragma unroll
        for (int it = 0; it < 2; ++it) {
            int row = lrow + it * 64;
            uint32_t dst = sb + buf * BUF_BYTES + sub * TILE_BYTES + row * TILE_STRIDE + lcb;
            cp16(dst, srcs[sub] + (size_t)(br4[sub] + row) * K + k0 + lel);
        }
}

template<int EPI>
__global__ __launch_bounds__(256, 2)
void mma_gemm(const __nv_bfloat16* __restrict__ AH, const __nv_bfloat16* __restrict__ AL,
              const __nv_bfloat16* __restrict__ BH, const __nv_bfloat16* __restrict__ BL,
              const __nv_bfloat16* __restrict__ A2H, const __nv_bfloat16* __restrict__ A2L,
              const __nv_bfloat16* __restrict__ B2H, const __nv_bfloat16* __restrict__ B2L,
              const float* __restrict__ bias,
              const float* __restrict__ e1, const float* __restrict__ e2,
              float* __restrict__ outF,
              __nv_bfloat16* __restrict__ outH, __nv_bfloat16* __restrict__ outL,
              int N, int K)
{
    extern __shared__ char smem[];
    const uint32_t sb = smem_u32(smem);
    const int tid = threadIdx.x, wid = tid >> 5, lane = tid & 31;
    const int bm = blockIdx.y * 128, bn = blockIdx.x * 128;
    const int wm = (wid & 3) * 32, wn = (wid >> 2) * 64;

    float acc[2][8][4];
#pragma unroll
    for (int i = 0; i < 2; i++)
#pragma unroll
        for (int j = 0; j < 8; j++)
#pragma unroll
            for (int k = 0; k < 4; k++) acc[i][j][k] = 0.f;

    const int a_row  = lane & 15;
    const int a_byte = (lane >> 4) * 16;
    const int bg     = lane >> 3;
    const int b_row  = (bg >> 1) * 8 + (lane & 7);
    const int b_byte = (bg & 1) * 16;

    const int kchunks = K / 32;
    const int nchunks = (EPI == 1 ? 2 : 1) * kchunks;

    #define SEL(c, ah_, al_, bh_, bl_, k0_)                                     \
        if (EPI == 1 && (c) >= kchunks) {                                       \
            ah_ = A2H; al_ = A2L; bh_ = B2H; bl_ = B2L; k0_ = ((c) - kchunks) * 32; \
        } else { ah_ = AH; al_ = AL; bh_ = BH; bl_ = BL; k0_ = (c) * 32; }

    {
        const __nv_bfloat16 *ah, *al, *bh, *bl; int k0;
        SEL(0, ah, al, bh, bl, k0);
        load_chunk_cp(sb, 0, tid, bm, bn, K, ah, al, bh, bl, k0);
        asm volatile("cp.async.commit_group;" ::: "memory");
    }

    for (int c = 0; c < nchunks; ++c) {
        const int buf = c & 1;
        if (c + 1 < nchunks) {
            const __nv_bfloat16 *ah, *al, *bh, *bl; int k0;
            SEL(c + 1, ah, al, bh, bl, k0);
            load_chunk_cp(sb, (c + 1) & 1, tid, bm, bn, K, ah, al, bh, bl, k0);
        }
        asm volatile("cp.async.commit_group;" ::: "memory");
        asm volatile("cp.async.wait_group 1;" ::: "memory");
        __syncthreads();

        const uint32_t tb = sb + buf * BUF_BYTES;
#pragma unroll
        for (int ks = 0; ks < 2; ++ks) {
            uint32_t af[2][4], bf[8][2], xf[2][4];
#pragma unroll
            for (int mt = 0; mt < 2; ++mt) {
                uint32_t ad = tb + (wm + mt * 16 + a_row) * TILE_STRIDE + ks * 32 + a_byte;
                LDSM4(af[mt], ad);
            }
#pragma unroll
            for (int j = 0; j < 4; ++j) {
                uint32_t ad = tb + 2 * TILE_BYTES + (wn + j * 16 + b_row) * TILE_STRIDE + ks * 32 + b_byte;
                uint32_t r[4]; LDSM4(r, ad);
                bf[2*j][0] = r[0]; bf[2*j][1] = r[1];
                bf[2*j+1][0] = r[2]; bf[2*j+1][1] = r[3];
            }
#pragma unroll
            for (int mt = 0; mt < 2; ++mt)
#pragma unroll
                for (int nt = 0; nt < 8; ++nt) MMA16816(acc[mt][nt], af[mt], bf[nt]);
#pragma unroll
            for (int mt = 0; mt < 2; ++mt) {
                uint32_t ad = tb + TILE_BYTES + (wm + mt * 16 + a_row) * TILE_STRIDE + ks * 32 + a_byte;
                LDSM4(xf[mt], ad);
            }
#pragma unroll
            for (int mt = 0; mt < 2; ++mt)
#pragma unroll
                for (int nt = 0; nt < 8; ++nt) MMA16816(acc[mt][nt], xf[mt], bf[nt]);
#pragma unroll
            for (int j = 0; j < 4; ++j) {
                uint32_t ad = tb + 3 * TILE_BYTES + (wn + j * 16 + b_row) * TILE_STRIDE + ks * 32 + b_byte;
                uint32_t r[4]; LDSM4(r, ad);
                bf[2*j][0] = r[0]; bf[2*j][1] = r[1];
                bf[2*j+1][0] = r[2]; bf[2*j+1][1] = r[3];
            }
#pragma unroll
            for (int mt = 0; mt < 2; ++mt)
#pragma unroll
                for (int nt = 0; nt < 8; ++nt) MMA16816(acc[mt][nt], af[mt], bf[nt]);
        }
        __syncthreads();
    }
    #undef SEL

    // ---- stage accumulators to SMEM (128 x 132 fp32), then fused epilogue ----
    float* stg = (float*)smem;
#pragma unroll
    for (int mt = 0; mt < 2; ++mt)
#pragma unroll
        for (int nt = 0; nt < 8; ++nt)
#pragma unroll
            for (int h = 0; h < 2; ++h) {
                int r  = wm + mt * 16 + (lane >> 2) + h * 8;
                int cc = wn + nt * 8 + (lane & 3) * 2;
                *(float2*)(stg + r * 132 + cc) =
                    make_float2(acc[mt][nt][h * 2], acc[mt][nt][h * 2 + 1]);
            }
    __syncthreads();

    for (int i = tid; i < 128 * 32; i += 256) {
        int r = i >> 5, c4 = (i & 31) * 4;
        float4 v = *(const float4*)(stg + r * 132 + c4);
        const int row = bm + r, col = bn + c4;
        if (EPI == 2) {
            const int co = col >> 1;
            float2 sk = *(const float2*)(e2 + (size_t)row * DMOD + co);
            float h2a = sk.x + (v.x + bias[co])     * sigmoid_f(v.y + e1[co]);
            float h2b = sk.y + (v.z + bias[co + 1]) * sigmoid_f(v.w + e1[co + 1]);
            uint32_t hh, ll;
            split_pair(h2a, h2b, hh, ll);
            size_t gi = (size_t)row * DMOD + co;
            *(uint32_t*)(outH + gi) = hh;
            *(uint32_t*)(outL + gi) = ll;
            continue;
        }
        if (EPI == 0) {
            if (bias) {
                float4 bb = *(const float4*)(bias + col);
                v.x += bb.x; v.y += bb.y; v.z += bb.z; v.w += bb.w;
            }
        } else if (EPI == 1) {
            float4 dd = *(const float4*)(e1 + col);
            float4 hh = *(const float4*)(e2 + (size_t)row * DMOD + col);
            v.x = gelu_tanh(v.x + dd.x * hh.x);
            v.y = gelu_tanh(v.y + dd.y * hh.y);
            v.z = gelu_tanh(v.z + dd.z * hh.z);
            v.w = gelu_tanh(v.w + dd.w * hh.w);
        }
        size_t gi = (size_t)row * N + col;
        if (outF) *(float4*)(outF + gi) = v;
        if (outH) {
            uint2 uh, ul;
            split_pair(v.x, v.y, uh.x, ul.x);
            split_pair(v.z, v.w, uh.y, ul.y);
            *(uint2*)(outH + gi) = uh;
            *(uint2*)(outL + gi) = ul;
        }
    }
}

// ---------------- LayerNorm (+ bf16 hi/lo) ----------------
__global__ __launch_bounds__(128)
void ln_kernel(const float* __restrict__ h, const float* __restrict__ g,
               const float* __restrict__ b, float* __restrict__ out,
               __nv_bfloat16* __restrict__ oh, __nv_bfloat16* __restrict__ ol)
{
    const int row = blockIdx.x, t = threadIdx.x;
    float4 v = ((const float4*)(h + (size_t)row * DMOD))[t];
    float s  = v.x + v.y + v.z + v.w;
    float sq = v.x*v.x + v.y*v.y + v.z*v.z + v.w*v.w;
#pragma unroll
    for (int o = 16; o > 0; o >>= 1) {
        s  += __shfl_down_sync(0xffffffff, s,  o);
        sq += __shfl_down_sync(0xffffffff, sq, o);
    }
    __shared__ float ss[4], ssq[4];
    const int w = t >> 5, l = t & 31;
    if (l == 0) { ss[w] = s; ssq[w] = sq; }
    __syncthreads();
    if (t == 0) {
        float S = ss[0]+ss[1]+ss[2]+ss[3], SQ = ssq[0]+ssq[1]+ssq[2]+ssq[3];
        float mu = S * (1.f/DMOD);
        ss[0] = mu;
        ssq[0] = rsqrtf(SQ * (1.f/DMOD) - mu*mu + 1e-5f);
    }
    __syncthreads();
    const float mu = ss[0], rstd = ssq[0];
    float4 gv = ((const float4*)g)[t], bv = ((const float4*)b)[t];
    float4 o4;
    o4.x = (v.x-mu)*rstd*gv.x + bv.x;
    o4.y = (v.y-mu)*rstd*gv.y + bv.y;
    o4.z = (v.z-mu)*rstd*gv.z + bv.z;
    o4.w = (v.w-mu)*rstd*gv.w + bv.w;
    size_t gi = (size_t)row * DMOD + t * 4;
    *(float4*)(out + gi) = o4;
    uint2 uh, ul;
    split_pair(o4.x, o4.y, uh.x, ul.x);
    split_pair(o4.z, o4.w, uh.y, ul.y);
    *(uint2*)(oh + gi) = uh;
    *(uint2*)(ol + gi) = ul;
}

// ---------------- chunked LinOSS-IM scan (interleaved Bu) ----------------
__device__ __forceinline__ void scan_params(int n, const float* __restrict__ A_diag,
                                            const float* __restrict__ ls,
                                            float& m11, float& m12, float& m21, float& m22,
                                            float& c1, float& c2)
{
    float Ad = fmaxf(A_diag[n], 0.f);
    float dt = 1.f / (1.f + expf(-ls[n]));
    float S  = 1.f / (1.f + dt*dt*Ad);
    m11 = 1.f - dt*dt*Ad*S; m12 = -dt*Ad*S; m21 = dt*S; m22 = S;
    c1 = m11*dt; c2 = m21*dt;
}

__global__ __launch_bounds__(256)
void scanA(const float* __restrict__ bu,
           const float* __restrict__ A_diag, const float* __restrict__ ls,
           float* __restrict__ st)
{
    const int n  = ((blockIdx.x & 1) << 8) + threadIdx.x;
    const int bg = blockIdx.x >> 1;
    const int g  = bg & (GCH - 1), b = bg >> 4;
    float m11, m12, m21, m22, c1, c2;
    scan_params(n, A_diag, ls, m11, m12, m21, m22, c1, c2);
    float zr = 0.f, zi = 0.f, xr = 0.f, xi = 0.f;
    size_t idx = ((size_t)b * LSEQ + (size_t)g * CLEN) * (2*DMOD) + 2*n;
    for (int t = 0; t < CLEN; t++, idx += 2*DMOD) {
        float2 bv = *(const float2*)(bu + idx);
        float nzr = fmaf(m11, zr, fmaf(m12, xr, c1 * bv.x));
        float nzi = fmaf(m11, zi, fmaf(m12, xi, c1 * bv.y));
        float nxr = fmaf(m21, zr, fmaf(m22, xr, c2 * bv.x));
        float nxi = fmaf(m21, zi, fmaf(m22, xi, c2 * bv.y));
        zr = nzr; zi = nzi; xr = nxr; xi = nxi;
    }
    int si = bg * DMOD + n;
    st[si] = zr; st[ST_PLANE + si] = xr;
    st[2*ST_PLANE + si] = zi; st[3*ST_PLANE + si] = xi;
}

__global__ __launch_bounds__(256)
void scanB(const float* __restrict__ A_diag, const float* __restrict__ ls,
           const float* __restrict__ st, float* __restrict__ init)
{
    const int tid = blockIdx.x * 256 + threadIdx.x;
    const int n = tid & (DMOD - 1), b = tid >> 9;
    float m11, m12, m21, m22, c1, c2;
    scan_params(n, A_diag, ls, m11, m12, m21, m22, c1, c2);
    float a11 = m11, a12 = m12, a21 = m21, a22 = m22;
#pragma unroll
    for (int i = 0; i < 7; i++) {
        float n11 = a11*a11 + a12*a21, n12 = a11*a12 + a12*a22;
        float n21 = a21*a11 + a22*a21, n22 = a21*a12 + a22*a22;
        a11 = n11; a12 = n12; a21 = n21; a22 = n22;
    }
    float pzr = 0.f, pxr = 0.f, pzi = 0.f, pxi = 0.f;
    for (int g = 0; g < GCH; g++) {
        int si = (b * GCH + g) * DMOD + n;
        init[si] = pzr; init[ST_PLANE + si] = pxr;
        init[2*ST_PLANE + si] = pzi; init[3*ST_PLANE + si] = pxi;
        float szr = st[si], sxr = st[ST_PLANE + si];
        float szi = st[2*ST_PLANE + si], sxi = st[3*ST_PLANE + si];
        float nzr = a11*pzr + a12*pxr + szr, nxr = a21*pzr + a22*pxr + sxr;
        float nzi = a11*pzi + a12*pxi + szi, nxi = a21*pzi + a22*pxi + sxi;
        pzr = nzr; pxr = nxr; pzi = nzi; pxi = nxi;
    }
}

__global__ __launch_bounds__(256)
void scanC(const float* __restrict__ bu,
           const float* __restrict__ A_diag, const float* __restrict__ ls,
           const float* __restrict__ init,
           __nv_bfloat16* __restrict__ xrh, __nv_bfloat16* __restrict__ xrl,
           __nv_bfloat16* __restrict__ xih, __nv_bfloat16* __restrict__ xil)
{
    const int n  = ((blockIdx.x & 1) << 8) + threadIdx.x;
    const int bg = blockIdx.x >> 1;
    const int g  = bg & (GCH - 1), b = bg >> 4;
    float m11, m12, m21, m22, c1, c2;
    scan_params(n, A_diag, ls, m11, m12, m21, m22, c1, c2);
    int si = bg * DMOD + n;
    float zr = init[si], xr = init[ST_PLANE + si];
    float zi = init[2*ST_PLANE + si], xi = init[3*ST_PLANE + si];
    size_t idx  = ((size_t)b * LSEQ + (size_t)g * CLEN) * (2*DMOD) + 2*n;
    size_t odx  = ((size_t)b * LSEQ + (size_t)g * CLEN) * DMOD + n;
    for (int t = 0; t < CLEN; t++, idx += 2*DMOD, odx += DMOD) {
        float2 bv = *(const float2*)(bu + idx);
        float nzr = fmaf(m11, zr, fmaf(m12, xr, c1 * bv.x));
        float nzi = fmaf(m11, zi, fmaf(m12, xi, c1 * bv.y));
        float nxr = fmaf(m21, zr, fmaf(m22, xr, c2 * bv.x));
        float nxi = fmaf(m21, zi, fmaf(m22, xi, c2 * bv.y));
        zr = nzr; zi = nzi; xr = nxr; xi = nxi;
        __nv_bfloat16 hr = __float2bfloat16(xr);
        __nv_bfloat16 hi = __float2bfloat16(xi);
        xrh[odx] = hr; xrl[odx] = __float2bfloat16(xr - __bfloat162float(hr));
        xih[odx] = hi; xil[odx] = __float2bfloat16(xi - __bfloat162float(hi));
    }
}

// ---------------------------------------------------------------------------
extern "C" void kernel_launch(void* const* d_in, const int* in_sizes, int n_in,
                              void* d_out, int out_size)
{
    const float* x      = (const float*)d_in[0];
    const float* W_in   = (const float*)d_in[1];
    const float* b_in   = (const float*)d_in[2];
    const float* W_enc  = (const float*)d_in[3];
    const float* b_enc  = (const float*)d_in[4];
    const float* ln_g   = (const float*)d_in[5];
    const float* ln_b   = (const float*)d_in[6];
    const float* A_diag = (const float*)d_in[7];
    const float* lstep  = (const float*)d_in[8];
    const float* B_re   = (const float*)d_in[9];
    const float* B_im   = (const float*)d_in[10];
    const float* C_re   = (const float*)d_in[11];
    const float* C_im   = (const float*)d_in[12];
    const float* Dv     = (const float*)d_in[13];
    const float* gw1    = (const float*)d_in[14];
    const float* gb1    = (const float*)d_in[15];
    const float* gw2    = (const float*)d_in[16];
    const float* gb2    = (const float*)d_in[17];
    const float* W_dec  = (const float*)d_in[18];
    const float* b_dec  = (const float*)d_in[19];
    const float* W_out  = (const float*)d_in[20];
    const float* b_out  = (const float*)d_in[21];
    float* out = (float*)d_out;

    #define SYM(T, v, s) T* v; cudaGetSymbolAddress((void**)&v, s)
    SYM(float, H, g_H); SYM(float, HN, g_HN); SYM(float, BU, g_BU);
    SYM(float, ST, g_ST); SYM(float, IN, g_IN);
    SYM(float, BCE, g_BCE); SYM(float, BOD, g_BOD);
    SYM(__nv_bfloat16, XH, g_XH);  SYM(__nv_bfloat16, XL, g_XL);
    SYM(__nv_bfloat16, HNH, g_HNH); SYM(__nv_bfloat16, HNL, g_HNL);
    SYM(__nv_bfloat16, XRH, g_XRH); SYM(__nv_bfloat16, XRL, g_XRL);
    SYM(__nv_bfloat16, XIH, g_XIH); SYM(__nv_bfloat16, XIL, g_XIL);
    SYM(__nv_bfloat16, YH, g_YH);   SYM(__nv_bfloat16, YL, g_YL);
    SYM(__nv_bfloat16, H2H, g_H2H); SYM(__nv_bfloat16, H2L, g_H2L);
    SYM(__nv_bfloat16, CEH, w_CEH);  SYM(__nv_bfloat16, CEL, w_CEL);
    SYM(__nv_bfloat16, BUH, w_BUH);  SYM(__nv_bfloat16, BUL, w_BUL);
    SYM(__nv_bfloat16, CRH, w_CRH);  SYM(__nv_bfloat16, CRL, w_CRL);
    SYM(__nv_bfloat16, CIH, w_CIH);  SYM(__nv_bfloat16, CIL, w_CIL);
    SYM(__nv_bfloat16, GLH, w_GLH);  SYM(__nv_bfloat16, GLL, w_GLL);
    SYM(__nv_bfloat16, ODH, w_ODH);  SYM(__nv_bfloat16, ODL, w_ODL);
    #undef SYM

    cudaFuncSetAttribute(mma_gemm<0>, cudaFuncAttributeMaxDynamicSharedMemorySize, GEMM_SMEM);
    cudaFuncSetAttribute(mma_gemm<1>, cudaFuncAttributeMaxDynamicSharedMemorySize, GEMM_SMEM);
    cudaFuncSetAttribute(mma_gemm<2>, cudaFuncAttributeMaxDynamicSharedMemorySize, GEMM_SMEM);

    // ---- weight folding (fast): W_ce = W_enc@W_in (512x128); W_od = W_out@W_dec (128x512) ----
    fold_gemm<<<dim3(DMOD, HIN/128), 128>>>(W_enc, W_in, DMOD, HIN, CEH, CEL);
    fold_gemm<<<dim3(HIN, DMOD/128), 128>>>(W_out, W_dec, DMOD, DMOD, ODH, ODL);
    fold_bias<<<DMOD/8, 256>>>(W_enc, b_in, b_enc, DMOD, DMOD, BCE);
    fold_bias<<<HIN/8, 256>>>(W_out, b_dec, b_out, DMOD, HIN, BOD);

    // ---- single batched conversion: remaining weights (with interleave) + x ----
    {
        const int qW = DMOD * DMOD / 4;     // 65536 quads
        const int qX = T_TOK * HIN / 4;     // 524288
        ConvArgs a;
        const float* srcs[NJOBS] = {B_re, B_im, C_re, C_im, gw1, gw2, x};
        __nv_bfloat16* dhs[NJOBS] = {BUH, BUH, CRH, CIH, GLH, GLH, XH};
        __nv_bfloat16* dls[NJOBS] = {BUL, BUL, CRL, CIL, GLL, GLL, XL};
        const int sizes[NJOBS]   = {qW, qW, qW, qW, qW, qW, qX};
        const int extras[NJOBS]  = {128, 128, 0, 0, 128, 128, 0};
        const int dbases[NJOBS]  = {0,   128, 0, 0, 0,   128, 0};
        int acc0 = 0;
        for (int j = 0; j < NJOBS; j++) {
            a.src[j] = (const float4*)srcs[j];
            a.dh[j] = (uint2*)dhs[j];
            a.dl[j] = (uint2*)dls[j];
            a.sgn[j] = (j == 3) ? -1.f : 1.f;     // C_im pre-negated
            a.extra[j] = extras[j];
            a.dbase[j] = dbases[j];
            a.start[j] = acc0;
            acc0 += sizes[j];
        }
        a.start[NJOBS] = acc0;
        conv_all<<<(acc0 + 255) / 256, 256>>>(a);
    }

    dim3 blk(256);
    dim3 g512(DMOD / 128, T_TOK / 128);       // 4 x 128
    dim3 g1024(2 * DMOD / 128, T_TOK / 128);  // 8 x 128 (fused N=1024)
    dim3 g128(HIN / 128, T_TOK / 128);        // 1 x 128

    // 1) folded in_proj+encoder (K=128) -> fp32 H (skip)
    mma_gemm<0><<<g512, blk, GEMM_SMEM>>>(XH, XL, CEH, CEL, 0,0,0,0, BCE, 0,0,
                                          H, nullptr, nullptr, DMOD, HIN);
    // 2) layernorm -> HN fp32 + bf16
    ln_kernel<<<T_TOK, 128>>>(H, ln_g, ln_b, HN, HNH, HNL);
    // 3) fused Bu projection (interleaved re/im, N=1024) -> fp32 BU
    mma_gemm<0><<<g1024, blk, GEMM_SMEM>>>(HNH, HNL, BUH, BUL, 0,0,0,0, nullptr, 0,0,
                                           BU, nullptr, nullptr, 2*DMOD, DMOD);
    // 4) chunked scan -> bf16 xs
    scanA<<<256, 256>>>(BU, A_diag, lstep, ST);
    scanB<<<16, 256>>>(A_diag, lstep, ST, IN);
    scanC<<<256, 256>>>(BU, A_diag, lstep, IN, XRH, XRL, XIH, XIL);
    // 5) y = gelu(xr@Cre^T + xi@(-Cim)^T + D*hn) -> bf16 Y
    mma_gemm<1><<<g512, blk, GEMM_SMEM>>>(XRH, XRL, CRH, CRL, XIH, XIL, CIH, CIL,
                                          nullptr, Dv, HN, nullptr, YH, YL, DMOD, DMOD);
    // 6) fused GLU (interleaved g1/g2, N=1024) -> bf16 H2 = skip + g1*sigmoid(g2)
    mma_gemm<2><<<g1024, blk, GEMM_SMEM>>>(YH, YL, GLH, GLL, 0,0,0,0, gb1, gb2, H,
                                           nullptr, H2H, H2L, 2*DMOD, DMOD);
    // 7) folded decoder+out_proj (N=128, K=512) -> fp32 out
    mma_gemm<0><<<g128, blk, GEMM_SMEM>>>(H2H, H2L, ODH, ODL, 0,0,0,0, BOD, 0,0,
                                          out, nullptr, nullptr, HIN, DMOD);
}

// round 17
// speedup vs baseline: 1.4381x; 1.0017x over previous
#include <cuda_runtime.h>
#include <cuda_bf16.h>
#include <math.h>
#include <stdint.h>

#define T_TOK 16384
#define DMOD  512
#define LSEQ  2048
#define BATCH 8
#define HIN   128
#define GCH   16
#define CLEN  128          // LSEQ / GCH
#define ST_PLANE (BATCH*GCH*DMOD)

// ---------------- scratch (__device__ globals; no cudaMalloc) ----------------
__device__ float g_H  [(size_t)T_TOK*DMOD];   // encoder out == skip (fp32)
__device__ float g_HN [(size_t)T_TOK*DMOD];   // layernorm out (fp32)
__device__ float g_BU [(size_t)T_TOK*2*DMOD]; // Bu interleaved (re,im) fp32
__device__ float g_ST [4*ST_PLANE];           // scan chunk states
__device__ float g_IN [4*ST_PLANE];           // scan chunk init states

// bf16 hi/lo activation pairs
__device__ __nv_bfloat16 g_XH [(size_t)T_TOK*HIN],  g_XL [(size_t)T_TOK*HIN];
__device__ __nv_bfloat16 g_HNH[(size_t)T_TOK*DMOD], g_HNL[(size_t)T_TOK*DMOD];
__device__ __nv_bfloat16 g_XRH[(size_t)T_TOK*DMOD], g_XRL[(size_t)T_TOK*DMOD];
__device__ __nv_bfloat16 g_XIH[(size_t)T_TOK*DMOD], g_XIL[(size_t)T_TOK*DMOD];
__device__ __nv_bfloat16 g_YH [(size_t)T_TOK*DMOD], g_YL [(size_t)T_TOK*DMOD];
__device__ __nv_bfloat16 g_H2H[(size_t)T_TOK*DMOD], g_H2L[(size_t)T_TOK*DMOD];

// bf16 hi/lo weight pairs
__device__ __nv_bfloat16 w_CEH [DMOD*HIN],    w_CEL [DMOD*HIN];   // folded W_enc@W_in
__device__ __nv_bfloat16 w_BUH [2*DMOD*DMOD], w_BUL [2*DMOD*DMOD]; // interleaved [B_re;B_im]
__device__ __nv_bfloat16 w_CRH [DMOD*DMOD],   w_CRL [DMOD*DMOD];
__device__ __nv_bfloat16 w_CIH [DMOD*DMOD],   w_CIL [DMOD*DMOD];   // pre-negated
__device__ __nv_bfloat16 w_GLH [2*DMOD*DMOD], w_GLL [2*DMOD*DMOD]; // interleaved [gw1;gw2]
__device__ __nv_bfloat16 w_ODH [HIN*DMOD],    w_ODL [HIN*DMOD];   // folded W_out@W_dec
__device__ float g_BCE[DMOD];   // folded bias: W_enc@b_in + b_enc
__device__ float g_BOD[HIN];    // folded bias: W_out@b_dec + b_out

// ---------------- helpers ----------------
__device__ __forceinline__ float gelu_tanh(float x) {
    float x3 = x * x * x;
    return 0.5f * x * (1.f + tanhf(0.7978845608028654f * (x + 0.044715f * x3)));
}
__device__ __forceinline__ float sigmoid_f(float x) { return 1.f / (1.f + expf(-x)); }

__device__ __forceinline__ void split_pair(float a, float b, uint32_t& h, uint32_t& l) {
    __nv_bfloat16 ha = __float2bfloat16(a), hb = __float2bfloat16(b);
    __nv_bfloat162 th; th.x = ha; th.y = hb;
    __nv_bfloat162 tl;
    tl.x = __float2bfloat16(a - __bfloat162float(ha));
    tl.y = __float2bfloat16(b - __bfloat162float(hb));
    h = *reinterpret_cast<uint32_t*>(&th);
    l = *reinterpret_cast<uint32_t*>(&tl);
}
__device__ __forceinline__ uint32_t smem_u32(const void* p) {
    uint32_t a;
    asm("{ .reg .u64 t; cvta.to.shared.u64 t, %1; cvt.u32.u64 %0, t; }" : "=r"(a) : "l"(p));
    return a;
}
__device__ __forceinline__ void cp16(uint32_t smem, const void* g) {
    asm volatile("cp.async.cg.shared.global [%0], [%1], 16;" :: "r"(smem), "l"(g));
}

#define LDSM4(r, addr)                                                          \
    asm volatile("ldmatrix.sync.aligned.m8n8.x4.shared.b16 {%0,%1,%2,%3}, [%4];"\
        : "=r"((r)[0]), "=r"((r)[1]), "=r"((r)[2]), "=r"((r)[3]) : "r"(addr))

#define MMA16816(d, a, b)                                                       \
    asm volatile("mma.sync.aligned.m16n8k16.row.col.f32.bf16.bf16.f32 "        \
        "{%0,%1,%2,%3}, {%4,%5,%6,%7}, {%8,%9}, {%0,%1,%2,%3};"                \
        : "+f"((d)[0]), "+f"((d)[1]), "+f"((d)[2]), "+f"((d)[3])               \
        : "r"((a)[0]), "r"((a)[1]), "r"((a)[2]), "r"((a)[3]),                  \
          "r"((b)[0]), "r"((b)[1]))

// ---------------- weight folding: C = A(M x J) @ B(J x N) -> bf16 hi/lo ----------------
// grid (M, N/128), block 128. Row broadcast A, coalesced B, 4 accumulator chains.
__global__ __launch_bounds__(128)
void fold_gemm(const float* __restrict__ A, const float* __restrict__ B,
               int J, int N,
               __nv_bfloat16* __restrict__ oh, __nv_bfloat16* __restrict__ ol)
{
    const int r = blockIdx.x;
    const int c = blockIdx.y * 128 + threadIdx.x;
    const float* Ar = A + (size_t)r * J;
    const float* Bc = B + c;
    float a0 = 0.f, a1 = 0.f, a2 = 0.f, a3 = 0.f;
    for (int j = 0; j < J; j += 4) {
        a0 = fmaf(Ar[j + 0], Bc[(size_t)(j + 0) * N], a0);
        a1 = fmaf(Ar[j + 1], Bc[(size_t)(j + 1) * N], a1);
        a2 = fmaf(Ar[j + 2], Bc[(size_t)(j + 2) * N], a2);
        a3 = fmaf(Ar[j + 3], Bc[(size_t)(j + 3) * N], a3);
    }
    float v = (a0 + a1) + (a2 + a3);
    __nv_bfloat16 h = __float2bfloat16(v);
    size_t gi = (size_t)r * N + c;
    oh[gi] = h;
    ol[gi] = __float2bfloat16(v - __bfloat162float(h));
}

// folded bias: out[i] = sum_j A[i,j]*bin[j] + badd[i]; one warp per row (coalesced)
__global__ __launch_bounds__(256)
void fold_bias(const float* __restrict__ A, const float* __restrict__ bin,
               const float* __restrict__ badd, int J, int M, float* __restrict__ out)
{
    const int warp = (blockIdx.x * 256 + threadIdx.x) >> 5;
    const int lane = threadIdx.x & 31;
    if (warp >= M) return;
    float acc = 0.f;
    for (int j = lane; j < J; j += 32)
        acc = fmaf(A[(size_t)warp * J + j], bin[j], acc);
#pragma unroll
    for (int o = 16; o > 0; o >>= 1) acc += __shfl_down_sync(0xffffffffu, acc, o);
    if (lane == 0) out[warp] = acc + badd[warp];
}

// ---------------- batched fp32 -> (hi, lo) bf16 conversion ----------------
// Per-job row remap for interleaved dests: dest_quad = off + (off>>7)*extra + dbase
#define NJOBS 7
struct ConvArgs {
    const float4* src[NJOBS];
    uint2* dh[NJOBS];
    uint2* dl[NJOBS];
    float sgn[NJOBS];
    int extra[NJOBS];
    int dbase[NJOBS];
    int start[NJOBS + 1];
};

__global__ __launch_bounds__(256)
void conv_all(ConvArgs a)
{
    int i = blockIdx.x * 256 + threadIdx.x;
    if (i >= a.start[NJOBS]) return;
    int j = 0;
#pragma unroll
    for (int k = 1; k < NJOBS; k++) j += (i >= a.start[k]);
    int off = i - a.start[j];
    float4 v = a.src[j][off];
    float s = a.sgn[j];
    int dq = off + (off >> 7) * a.extra[j] + a.dbase[j];
    uint2 uh, ul;
    split_pair(s * v.x, s * v.y, uh.x, ul.x);
    split_pair(s * v.z, s * v.w, uh.y, ul.y);
    a.dh[j][dq] = uh;
    a.dl[j][dq] = ul;
}

// ---------------- split-bf16 GEMM on the tensor pipe (mma.sync) ----------------
// C[m,n] = sum_k A[m,k]*W[n,k]; A=AH+AL, W=BH+BL (bf16 splits); fp32 accum.
// 3-term: ah*bh + al*bh + ah*bl.
// CTA tile 128x128, K-chunk 32, cp.async double-buffered (2 x 40KB SMEM).
// EPI 0: v = acc (+bias[col]); store fp32 and/or bf16 hi/lo
// EPI 1: dual accumulate (A,W)+(A2,W2); v = gelu(acc + e1[col]*e2[row,col])
// EPI 2: GLU-pair interleaved: h2 = e2 + (acc1+bias)*sigmoid(acc2+e1), half-width out
#define TILE_STRIDE 80
#define TILE_BYTES  10240
#define BUF_BYTES   40960
#define GEMM_SMEM   (2*BUF_BYTES)

__device__ __forceinline__ void load_chunk_cp(
    uint32_t sb, int buf, int tid, int bm, int bn, int K,
    const __nv_bfloat16* ah, const __nv_bfloat16* al,
    const __nv_bfloat16* bh, const __nv_bfloat16* bl, int k0)
{
    const int lrow = tid >> 2;
    const int lcb  = (tid & 3) * 16;
    const int lel  = lcb >> 1;
    const __nv_bfloat16* srcs[4] = {ah, al, bh, bl};
    const int br4[4] = {bm, bm, bn, bn};
#pragma unroll
    for (int sub = 0; sub < 4; ++sub)
#pragma unroll
        for (int it = 0; it < 2; ++it) {
            int row = lrow + it * 64;
            uint32_t dst = sb + buf * BUF_BYTES + sub * TILE_BYTES + row * TILE_STRIDE + lcb;
            cp16(dst, srcs[sub] + (size_t)(br4[sub] + row) * K + k0 + lel);
        }
}

template<int EPI>
__global__ __launch_bounds__(256, 2)
void mma_gemm(const __nv_bfloat16* __restrict__ AH, const __nv_bfloat16* __restrict__ AL,
              const __nv_bfloat16* __restrict__ BH, const __nv_bfloat16* __restrict__ BL,
              const __nv_bfloat16* __restrict__ A2H, const __nv_bfloat16* __restrict__ A2L,
              const __nv_bfloat16* __restrict__ B2H, const __nv_bfloat16* __restrict__ B2L,
              const float* __restrict__ bias,
              const float* __restrict__ e1, const float* __restrict__ e2,
              float* __restrict__ outF,
              __nv_bfloat16* __restrict__ outH, __nv_bfloat16* __restrict__ outL,
              int N, int K)
{
    extern __shared__ char smem[];
    const uint32_t sb = smem_u32(smem);
    const int tid = threadIdx.x, wid = tid >> 5, lane = tid & 31;
    const int bm = blockIdx.y * 128, bn = blockIdx.x * 128;
    const int wm = (wid & 3) * 32, wn = (wid >> 2) * 64;

    float acc[2][8][4];
#pragma unroll
    for (int i = 0; i < 2; i++)
#pragma unroll
        for (int j = 0; j < 8; j++)
#pragma unroll
            for (int k = 0; k < 4; k++) acc[i][j][k] = 0.f;

    const int a_row  = lane & 15;
    const int a_byte = (lane >> 4) * 16;
    const int bg     = lane >> 3;
    const int b_row  = (bg >> 1) * 8 + (lane & 7);
    const int b_byte = (bg & 1) * 16;

    const int kchunks = K / 32;
    const int nchunks = (EPI == 1 ? 2 : 1) * kchunks;

    #define SEL(c, ah_, al_, bh_, bl_, k0_)                                     \
        if (EPI == 1 && (c) >= kchunks) {                                       \
            ah_ = A2H; al_ = A2L; bh_ = B2H; bl_ = B2L; k0_ = ((c) - kchunks) * 32; \
        } else { ah_ = AH; al_ = AL; bh_ = BH; bl_ = BL; k0_ = (c) * 32; }

    {
        const __nv_bfloat16 *ah, *al, *bh, *bl; int k0;
        SEL(0, ah, al, bh, bl, k0);
        load_chunk_cp(sb, 0, tid, bm, bn, K, ah, al, bh, bl, k0);
        asm volatile("cp.async.commit_group;" ::: "memory");
    }

    for (int c = 0; c < nchunks; ++c) {
        const int buf = c & 1;
        if (c + 1 < nchunks) {
            const __nv_bfloat16 *ah, *al, *bh, *bl; int k0;
            SEL(c + 1, ah, al, bh, bl, k0);
            load_chunk_cp(sb, (c + 1) & 1, tid, bm, bn, K, ah, al, bh, bl, k0);
        }
        asm volatile("cp.async.commit_group;" ::: "memory");
        asm volatile("cp.async.wait_group 1;" ::: "memory");
        __syncthreads();

        const uint32_t tb = sb + buf * BUF_BYTES;
#pragma unroll
        for (int ks = 0; ks < 2; ++ks) {
            uint32_t af[2][4], bf[8][2], xf[2][4];
#pragma unroll
            for (int mt = 0; mt < 2; ++mt) {
                uint32_t ad = tb + (wm + mt * 16 + a_row) * TILE_STRIDE + ks * 32 + a_byte;
                LDSM4(af[mt], ad);
            }
#pragma unroll
            for (int j = 0; j < 4; ++j) {
                uint32_t ad = tb + 2 * TILE_BYTES + (wn + j * 16 + b_row) * TILE_STRIDE + ks * 32 + b_byte;
                uint32_t r[4]; LDSM4(r, ad);
                bf[2*j][0] = r[0]; bf[2*j][1] = r[1];
                bf[2*j+1][0] = r[2]; bf[2*j+1][1] = r[3];
            }
#pragma unroll
            for (int mt = 0; mt < 2; ++mt)
#pragma unroll
                for (int nt = 0; nt < 8; ++nt) MMA16816(acc[mt][nt], af[mt], bf[nt]);
#pragma unroll
            for (int mt = 0; mt < 2; ++mt) {
                uint32_t ad = tb + TILE_BYTES + (wm + mt * 16 + a_row) * TILE_STRIDE + ks * 32 + a_byte;
                LDSM4(xf[mt], ad);
            }
#pragma unroll
            for (int mt = 0; mt < 2; ++mt)
#pragma unroll
                for (int nt = 0; nt < 8; ++nt) MMA16816(acc[mt][nt], xf[mt], bf[nt]);
#pragma unroll
            for (int j = 0; j < 4; ++j) {
                uint32_t ad = tb + 3 * TILE_BYTES + (wn + j * 16 + b_row) * TILE_STRIDE + ks * 32 + b_byte;
                uint32_t r[4]; LDSM4(r, ad);
                bf[2*j][0] = r[0]; bf[2*j][1] = r[1];
                bf[2*j+1][0] = r[2]; bf[2*j+1][1] = r[3];
            }
#pragma unroll
            for (int mt = 0; mt < 2; ++mt)
#pragma unroll
                for (int nt = 0; nt < 8; ++nt) MMA16816(acc[mt][nt], af[mt], bf[nt]);
        }
        __syncthreads();
    }
    #undef SEL

    // ---- stage accumulators to SMEM (128 x 132 fp32), then fused epilogue ----
    float* stg = (float*)smem;
#pragma unroll
    for (int mt = 0; mt < 2; ++mt)
#pragma unroll
        for (int nt = 0; nt < 8; ++nt)
#pragma unroll
            for (int h = 0; h < 2; ++h) {
                int r  = wm + mt * 16 + (lane >> 2) + h * 8;
                int cc = wn + nt * 8 + (lane & 3) * 2;
                *(float2*)(stg + r * 132 + cc) =
                    make_float2(acc[mt][nt][h * 2], acc[mt][nt][h * 2 + 1]);
            }
    __syncthreads();

    for (int i = tid; i < 128 * 32; i += 256) {
        int r = i >> 5, c4 = (i & 31) * 4;
        float4 v = *(const float4*)(stg + r * 132 + c4);
        const int row = bm + r, col = bn + c4;
        if (EPI == 2) {
            const int co = col >> 1;
            float2 sk = *(const float2*)(e2 + (size_t)row * DMOD + co);
            float h2a = sk.x + (v.x + bias[co])     * sigmoid_f(v.y + e1[co]);
            float h2b = sk.y + (v.z + bias[co + 1]) * sigmoid_f(v.w + e1[co + 1]);
            uint32_t hh, ll;
            split_pair(h2a, h2b, hh, ll);
            size_t gi = (size_t)row * DMOD + co;
            *(uint32_t*)(outH + gi) = hh;
            *(uint32_t*)(outL + gi) = ll;
            continue;
        }
        if (EPI == 0) {
            if (bias) {
                float4 bb = *(const float4*)(bias + col);
                v.x += bb.x; v.y += bb.y; v.z += bb.z; v.w += bb.w;
            }
        } else if (EPI == 1) {
            float4 dd = *(const float4*)(e1 + col);
            float4 hh = *(const float4*)(e2 + (size_t)row * DMOD + col);
            v.x = gelu_tanh(v.x + dd.x * hh.x);
            v.y = gelu_tanh(v.y + dd.y * hh.y);
            v.z = gelu_tanh(v.z + dd.z * hh.z);
            v.w = gelu_tanh(v.w + dd.w * hh.w);
        }
        size_t gi = (size_t)row * N + col;
        if (outF) *(float4*)(outF + gi) = v;
        if (outH) {
            uint2 uh, ul;
            split_pair(v.x, v.y, uh.x, ul.x);
            split_pair(v.z, v.w, uh.y, ul.y);
            *(uint2*)(outH + gi) = uh;
            *(uint2*)(outL + gi) = ul;
        }
    }
}

// ---------------- LayerNorm (+ bf16 hi/lo) ----------------
__global__ __launch_bounds__(128)
void ln_kernel(const float* __restrict__ h, const float* __restrict__ g,
               const float* __restrict__ b, float* __restrict__ out,
               __nv_bfloat16* __restrict__ oh, __nv_bfloat16* __restrict__ ol)
{
    const int row = blockIdx.x, t = threadIdx.x;
    float4 v = ((const float4*)(h + (size_t)row * DMOD))[t];
    float s  = v.x + v.y + v.z + v.w;
    float sq = v.x*v.x + v.y*v.y + v.z*v.z + v.w*v.w;
#pragma unroll
    for (int o = 16; o > 0; o >>= 1) {
        s  += __shfl_down_sync(0xffffffff, s,  o);
        sq += __shfl_down_sync(0xffffffff, sq, o);
    }
    __shared__ float ss[4], ssq[4];
    const int w = t >> 5, l = t & 31;
    if (l == 0) { ss[w] = s; ssq[w] = sq; }
    __syncthreads();
    if (t == 0) {
        float S = ss[0]+ss[1]+ss[2]+ss[3], SQ = ssq[0]+ssq[1]+ssq[2]+ssq[3];
        float mu = S * (1.f/DMOD);
        ss[0] = mu;
        ssq[0] = rsqrtf(SQ * (1.f/DMOD) - mu*mu + 1e-5f);
    }
    __syncthreads();
    const float mu = ss[0], rstd = ssq[0];
    float4 gv = ((const float4*)g)[t], bv = ((const float4*)b)[t];
    float4 o4;
    o4.x = (v.x-mu)*rstd*gv.x + bv.x;
    o4.y = (v.y-mu)*rstd*gv.y + bv.y;
    o4.z = (v.z-mu)*rstd*gv.z + bv.z;
    o4.w = (v.w-mu)*rstd*gv.w + bv.w;
    size_t gi = (size_t)row * DMOD + t * 4;
    *(float4*)(out + gi) = o4;
    uint2 uh, ul;
    split_pair(o4.x, o4.y, uh.x, ul.x);
    split_pair(o4.z, o4.w, uh.y, ul.y);
    *(uint2*)(oh + gi) = uh;
    *(uint2*)(ol + gi) = ul;
}

// ---------------- chunked LinOSS-IM scan (interleaved Bu) ----------------
__device__ __forceinline__ void scan_params(int n, const float* __restrict__ A_diag,
                                            const float* __restrict__ ls,
                                            float& m11, float& m12, float& m21, float& m22,
                                            float& c1, float& c2)
{
    float Ad = fmaxf(A_diag[n], 0.f);
    float dt = 1.f / (1.f + expf(-ls[n]));
    float S  = 1.f / (1.f + dt*dt*Ad);
    m11 = 1.f - dt*dt*Ad*S; m12 = -dt*Ad*S; m21 = dt*S; m22 = S;
    c1 = m11*dt; c2 = m21*dt;
}

__global__ __launch_bounds__(256)
void scanA(const float* __restrict__ bu,
           const float* __restrict__ A_diag, const float* __restrict__ ls,
           float* __restrict__ st)
{
    const int n  = ((blockIdx.x & 1) << 8) + threadIdx.x;
    const int bg = blockIdx.x >> 1;
    const int g  = bg & (GCH - 1), b = bg >> 4;
    float m11, m12, m21, m22, c1, c2;
    scan_params(n, A_diag, ls, m11, m12, m21, m22, c1, c2);
    float zr = 0.f, zi = 0.f, xr = 0.f, xi = 0.f;
    size_t idx = ((size_t)b * LSEQ + (size_t)g * CLEN) * (2*DMOD) + 2*n;
    for (int t = 0; t < CLEN; t++, idx += 2*DMOD) {
        float2 bv = *(const float2*)(bu + idx);
        float nzr = fmaf(m11, zr, fmaf(m12, xr, c1 * bv.x));
        float nzi = fmaf(m11, zi, fmaf(m12, xi, c1 * bv.y));
        float nxr = fmaf(m21, zr, fmaf(m22, xr, c2 * bv.x));
        float nxi = fmaf(m21, zi, fmaf(m22, xi, c2 * bv.y));
        zr = nzr; zi = nzi; xr = nxr; xi = nxi;
    }
    int si = bg * DMOD + n;
    st[si] = zr; st[ST_PLANE + si] = xr;
    st[2*ST_PLANE + si] = zi; st[3*ST_PLANE + si] = xi;
}

__global__ __launch_bounds__(256)
void scanB(const float* __restrict__ A_diag, const float* __restrict__ ls,
           const float* __restrict__ st, float* __restrict__ init)
{
    const int tid = blockIdx.x * 256 + threadIdx.x;
    const int n = tid & (DMOD - 1), b = tid >> 9;
    float m11, m12, m21, m22, c1, c2;
    scan_params(n, A_diag, ls, m11, m12, m21, m22, c1, c2);
    float a11 = m11, a12 = m12, a21 = m21, a22 = m22;
#pragma unroll
    for (int i = 0; i < 7; i++) {
        float n11 = a11*a11 + a12*a21, n12 = a11*a12 + a12*a22;
        float n21 = a21*a11 + a22*a21, n22 = a21*a12 + a22*a22;
        a11 = n11; a12 = n12; a21 = n21; a22 = n22;
    }
    float pzr = 0.f, pxr = 0.f, pzi = 0.f, pxi = 0.f;
    for (int g = 0; g < GCH; g++) {
        int si = (b * GCH + g) * DMOD + n;
        init[si] = pzr; init[ST_PLANE + si] = pxr;
        init[2*ST_PLANE + si] = pzi; init[3*ST_PLANE + si] = pxi;
        float szr = st[si], sxr = st[ST_PLANE + si];
        float szi = st[2*ST_PLANE + si], sxi = st[3*ST_PLANE + si];
        float nzr = a11*pzr + a12*pxr + szr, nxr = a21*pzr + a22*pxr + sxr;
        float nzi = a11*pzi + a12*pxi + szi, nxi = a21*pzi + a22*pxi + sxi;
        pzr = nzr; pxr = nxr; pzi = nzi; pxi = nxi;
    }
}

__global__ __launch_bounds__(256)
void scanC(const float* __restrict__ bu,
           const float* __restrict__ A_diag, const float* __restrict__ ls,
           const float* __restrict__ init,
           __nv_bfloat16* __restrict__ xrh, __nv_bfloat16* __restrict__ xrl,
           __nv_bfloat16* __restrict__ xih, __nv_bfloat16* __restrict__ xil)
{
    const int n  = ((blockIdx.x & 1) << 8) + threadIdx.x;
    const int bg = blockIdx.x >> 1;
    const int g  = bg & (GCH - 1), b = bg >> 4;
    float m11, m12, m21, m22, c1, c2;
    scan_params(n, A_diag, ls, m11, m12, m21, m22, c1, c2);
    int si = bg * DMOD + n;
    float zr = init[si], xr = init[ST_PLANE + si];
    float zi = init[2*ST_PLANE + si], xi = init[3*ST_PLANE + si];
    size_t idx  = ((size_t)b * LSEQ + (size_t)g * CLEN) * (2*DMOD) + 2*n;
    size_t odx  = ((size_t)b * LSEQ + (size_t)g * CLEN) * DMOD + n;
    for (int t = 0; t < CLEN; t++, idx += 2*DMOD, odx += DMOD) {
        float2 bv = *(const float2*)(bu + idx);
        float nzr = fmaf(m11, zr, fmaf(m12, xr, c1 * bv.x));
        float nzi = fmaf(m11, zi, fmaf(m12, xi, c1 * bv.y));
        float nxr = fmaf(m21, zr, fmaf(m22, xr, c2 * bv.x));
        float nxi = fmaf(m21, zi, fmaf(m22, xi, c2 * bv.y));
        zr = nzr; zi = nzi; xr = nxr; xi = nxi;
        __nv_bfloat16 hr = __float2bfloat16(xr);
        __nv_bfloat16 hi = __float2bfloat16(xi);
        xrh[odx] = hr; xrl[odx] = __float2bfloat16(xr - __bfloat162float(hr));
        xih[odx] = hi; xil[odx] = __float2bfloat16(xi - __bfloat162float(hi));
    }
}

// ---------------------------------------------------------------------------
extern "C" void kernel_launch(void* const* d_in, const int* in_sizes, int n_in,
                              void* d_out, int out_size)
{
    const float* x      = (const float*)d_in[0];
    const float* W_in   = (const float*)d_in[1];
    const float* b_in   = (const float*)d_in[2];
    const float* W_enc  = (const float*)d_in[3];
    const float* b_enc  = (const float*)d_in[4];
    const float* ln_g   = (const float*)d_in[5];
    const float* ln_b   = (const float*)d_in[6];
    const float* A_diag = (const float*)d_in[7];
    const float* lstep  = (const float*)d_in[8];
    const float* B_re   = (const float*)d_in[9];
    const float* B_im   = (const float*)d_in[10];
    const float* C_re   = (const float*)d_in[11];
    const float* C_im   = (const float*)d_in[12];
    const float* Dv     = (const float*)d_in[13];
    const float* gw1    = (const float*)d_in[14];
    const float* gb1    = (const float*)d_in[15];
    const float* gw2    = (const float*)d_in[16];
    const float* gb2    = (const float*)d_in[17];
    const float* W_dec  = (const float*)d_in[18];
    const float* b_dec  = (const float*)d_in[19];
    const float* W_out  = (const float*)d_in[20];
    const float* b_out  = (const float*)d_in[21];
    float* out = (float*)d_out;

    #define SYM(T, v, s) T* v; cudaGetSymbolAddress((void**)&v, s)
    SYM(float, H, g_H); SYM(float, HN, g_HN); SYM(float, BU, g_BU);
    SYM(float, ST, g_ST); SYM(float, IN, g_IN);
    SYM(float, BCE, g_BCE); SYM(float, BOD, g_BOD);
    SYM(__nv_bfloat16, XH, g_XH);  SYM(__nv_bfloat16, XL, g_XL);
    SYM(__nv_bfloat16, HNH, g_HNH); SYM(__nv_bfloat16, HNL, g_HNL);
    SYM(__nv_bfloat16, XRH, g_XRH); SYM(__nv_bfloat16, XRL, g_XRL);
    SYM(__nv_bfloat16, XIH, g_XIH); SYM(__nv_bfloat16, XIL, g_XIL);
    SYM(__nv_bfloat16, YH, g_YH);   SYM(__nv_bfloat16, YL, g_YL);
    SYM(__nv_bfloat16, H2H, g_H2H); SYM(__nv_bfloat16, H2L, g_H2L);
    SYM(__nv_bfloat16, CEH, w_CEH);  SYM(__nv_bfloat16, CEL, w_CEL);
    SYM(__nv_bfloat16, BUH, w_BUH);  SYM(__nv_bfloat16, BUL, w_BUL);
    SYM(__nv_bfloat16, CRH, w_CRH);  SYM(__nv_bfloat16, CRL, w_CRL);
    SYM(__nv_bfloat16, CIH, w_CIH);  SYM(__nv_bfloat16, CIL, w_CIL);
    SYM(__nv_bfloat16, GLH, w_GLH);  SYM(__nv_bfloat16, GLL, w_GLL);
    SYM(__nv_bfloat16, ODH, w_ODH);  SYM(__nv_bfloat16, ODL, w_ODL);
    #undef SYM

    cudaFuncSetAttribute(mma_gemm<0>, cudaFuncAttributeMaxDynamicSharedMemorySize, GEMM_SMEM);
    cudaFuncSetAttribute(mma_gemm<1>, cudaFuncAttributeMaxDynamicSharedMemorySize, GEMM_SMEM);
    cudaFuncSetAttribute(mma_gemm<2>, cudaFuncAttributeMaxDynamicSharedMemorySize, GEMM_SMEM);

    // ---- weight folding (fast): W_ce = W_enc@W_in (512x128); W_od = W_out@W_dec (128x512) ----
    fold_gemm<<<dim3(DMOD, HIN/128), 128>>>(W_enc, W_in, DMOD, HIN, CEH, CEL);
    fold_gemm<<<dim3(HIN, DMOD/128), 128>>>(W_out, W_dec, DMOD, DMOD, ODH, ODL);
    fold_bias<<<DMOD/8, 256>>>(W_enc, b_in, b_enc, DMOD, DMOD, BCE);
    fold_bias<<<HIN/8, 256>>>(W_out, b_dec, b_out, DMOD, HIN, BOD);

    // ---- single batched conversion: remaining weights (with interleave) + x ----
    {
        const int qW = DMOD * DMOD / 4;     // 65536 quads
        const int qX = T_TOK * HIN / 4;     // 524288
        ConvArgs a;
        const float* srcs[NJOBS] = {B_re, B_im, C_re, C_im, gw1, gw2, x};
        __nv_bfloat16* dhs[NJOBS] = {BUH, BUH, CRH, CIH, GLH, GLH, XH};
        __nv_bfloat16* dls[NJOBS] = {BUL, BUL, CRL, CIL, GLL, GLL, XL};
        const int sizes[NJOBS]   = {qW, qW, qW, qW, qW, qW, qX};
        const int extras[NJOBS]  = {128, 128, 0, 0, 128, 128, 0};
        const int dbases[NJOBS]  = {0,   128, 0, 0, 0,   128, 0};
        int acc0 = 0;
        for (int j = 0; j < NJOBS; j++) {
            a.src[j] = (const float4*)srcs[j];
            a.dh[j] = (uint2*)dhs[j];
            a.dl[j] = (uint2*)dls[j];
            a.sgn[j] = (j == 3) ? -1.f : 1.f;     // C_im pre-negated
            a.extra[j] = extras[j];
            a.dbase[j] = dbases[j];
            a.start[j] = acc0;
            acc0 += sizes[j];
        }
        a.start[NJOBS] = acc0;
        conv_all<<<(acc0 + 255) / 256, 256>>>(a);
    }

    dim3 blk(256);
    dim3 g512(DMOD / 128, T_TOK / 128);       // 4 x 128
    dim3 g1024(2 * DMOD / 128, T_TOK / 128);  // 8 x 128 (fused N=1024)
    dim3 g128(HIN / 128, T_TOK / 128);        // 1 x 128

    // 1) folded in_proj+encoder (K=128) -> fp32 H (skip)
    mma_gemm<0><<<g512, blk, GEMM_SMEM>>>(XH, XL, CEH, CEL, 0,0,0,0, BCE, 0,0,
                                          H, nullptr, nullptr, DMOD, HIN);
    // 2) layernorm -> HN fp32 + bf16
    ln_kernel<<<T_TOK, 128>>>(H, ln_g, ln_b, HN, HNH, HNL);
    // 3) fused Bu projection (interleaved re/im, N=1024) -> fp32 BU
    mma_gemm<0><<<g1024, blk, GEMM_SMEM>>>(HNH, HNL, BUH, BUL, 0,0,0,0, nullptr, 0,0,
                                           BU, nullptr, nullptr, 2*DMOD, DMOD);
    // 4) chunked scan -> bf16 xs
    scanA<<<256, 256>>>(BU, A_diag, lstep, ST);
    scanB<<<16, 256>>>(A_diag, lstep, ST, IN);
    scanC<<<256, 256>>>(BU, A_diag, lstep, IN, XRH, XRL, XIH, XIL);
    // 5) y = gelu(xr@Cre^T + xi@(-Cim)^T + D*hn) -> bf16 Y
    mma_gemm<1><<<g512, blk, GEMM_SMEM>>>(XRH, XRL, CRH, CRL, XIH, XIL, CIH, CIL,
                                          nullptr, Dv, HN, nullptr, YH, YL, DMOD, DMOD);
    // 6) fused GLU (interleaved g1/g2, N=1024) -> bf16 H2 = skip + g1*sigmoid(g2)
    mma_gemm<2><<<g1024, blk, GEMM_SMEM>>>(YH, YL, GLH, GLL, 0,0,0,0, gb1, gb2, H,
                                           nullptr, H2H, H2L, 2*DMOD, DMOD);
    // 7) folded decoder+out_proj (N=128, K=512) -> fp32 out
    mma_gemm<0><<<g128, blk, GEMM_SMEM>>>(H2H, H2L, ODH, ODL, 0,0,0,0, BOD, 0,0,
                                          out, nullptr, nullptr, HIN, DMOD);
}